// round 1
// baseline (speedup 1.0000x reference)
#include <cuda_runtime.h>
#include <cuda_bf16.h>
#include <math.h>

// Problem constants
#define BB 2
#define SS 2048
#define DD 1024
#define HH 16
#define DH 64

// ---------------- scratch (static device globals; no allocation) -------------
__device__ float g_qkv[BB * SS * 3 * DD];             // 50 MB
__device__ float g_q[BB * HH * SS * DH];              // 16 MB
__device__ float g_k[BB * HH * SS * DH];              // 16 MB
__device__ float g_v[BB * HH * SS * DH];              // 16 MB
__device__ float g_sc[(size_t)BB * HH * SS * SS];     // 536 MB (biasT -> scores -> attn, in place)
__device__ float g_ao[BB * SS * DD];                  // 16 MB
__device__ int   g_mask_kind;                         // 0=u8, 1=i32, 2=f32

// ---------------- mask dtype detection ---------------------------------------
// kv_mask is a jax bool; its on-device dtype is ambiguous. Scan the first
// 4096 bytes (valid under every interpretation): packed u8 bools give words
// with bytes beyond byte0 set; f32 gives 0x3F800000; i32 gives only {0,1}.
__global__ void detect_mask_kind_kernel(const unsigned int* __restrict__ m) {
    bool sawFloat = false, sawBig = false;
    for (int i = 0; i < 1024; i++) {
        unsigned int w = m[i];
        if (w == 0x3F800000u) sawFloat = true;
        else if (w > 1u) sawBig = true;
    }
    g_mask_kind = sawFloat ? 2 : (sawBig ? 0 : 1);
}

__device__ __forceinline__ bool mask_at(const void* mask, int kind, int idx) {
    if (kind == 0) return ((const unsigned char*)mask)[idx] != 0;
    if (kind == 1) return ((const int*)mask)[idx] != 0;
    return ((const float*)mask)[idx] != 0.0f;
}

// ---------------- generic SGEMM: C[M,N] = A[M,K] @ B[K,N] + bias[N] ----------
// 128x128 tile, 8x8 per thread, BK=8, 256 threads. M%128==0, N%128==0, K%8==0.
__global__ __launch_bounds__(256) void sgemm_bias_kernel(
    const float* __restrict__ A, const float* __restrict__ B,
    const float* __restrict__ bias, float* __restrict__ C,
    int M, int N, int K)
{
    constexpr int BM = 128, BN = 128, BK = 8;
    __shared__ float As[BK][BM];
    __shared__ float Bs[BK][BN];
    const int tid = threadIdx.x;
    const int tx = tid & 15, ty = tid >> 4;
    const int rowC0 = blockIdx.y * BM + ty * 8;
    const int colC0 = blockIdx.x * BN + tx * 8;

    float acc[8][8];
#pragma unroll
    for (int i = 0; i < 8; i++)
#pragma unroll
        for (int j = 0; j < 8; j++) acc[i][j] = 0.f;

    const int aRow = tid >> 1, aCol = (tid & 1) * 4;
    const int bRow = tid >> 5, bCol = (tid & 31) * 4;
    const float* Ag = A + ((size_t)blockIdx.y * BM + aRow) * K + aCol;
    const float* Bg = B + (size_t)bRow * N + blockIdx.x * BN + bCol;

    for (int k0 = 0; k0 < K; k0 += BK) {
        float4 av = *(const float4*)(Ag + k0);
        As[aCol + 0][aRow] = av.x; As[aCol + 1][aRow] = av.y;
        As[aCol + 2][aRow] = av.z; As[aCol + 3][aRow] = av.w;
        float4 bv = *(const float4*)(Bg + (size_t)k0 * N);
        *(float4*)&Bs[bRow][bCol] = bv;
        __syncthreads();
#pragma unroll
        for (int kk = 0; kk < BK; kk++) {
            float ar[8], br[8];
#pragma unroll
            for (int i = 0; i < 8; i++) ar[i] = As[kk][ty * 8 + i];
            float4 b0 = *(const float4*)&Bs[kk][tx * 8];
            float4 b1 = *(const float4*)&Bs[kk][tx * 8 + 4];
            br[0] = b0.x; br[1] = b0.y; br[2] = b0.z; br[3] = b0.w;
            br[4] = b1.x; br[5] = b1.y; br[6] = b1.z; br[7] = b1.w;
#pragma unroll
            for (int i = 0; i < 8; i++)
#pragma unroll
                for (int j = 0; j < 8; j++) acc[i][j] += ar[i] * br[j];
        }
        __syncthreads();
    }
#pragma unroll
    for (int i = 0; i < 8; i++) {
        const int r = rowC0 + i;
#pragma unroll
        for (int j = 0; j < 8; j += 4) {
            const int c = colC0 + j;
            float4 o;
            o.x = acc[i][j + 0] + bias[c + 0];
            o.y = acc[i][j + 1] + bias[c + 1];
            o.z = acc[i][j + 2] + bias[c + 2];
            o.w = acc[i][j + 3] + bias[c + 3];
            *(float4*)(C + (size_t)r * N + c) = o;
        }
    }
}

// ---------------- RoPE + head split ------------------------------------------
// One thread per (b, s, h, j) with j in [0,32): handles the rotated pair
// (j, j+32) of q and k, plus the v copy. Output layout [B,H,S,DH].
__global__ __launch_bounds__(256) void rope_split_kernel() {
    const int i = blockIdx.x * 256 + threadIdx.x;   // < 2^21
    const int j = i & 31;
    const int h = (i >> 5) & 15;
    const int s = (i >> 9) & 2047;
    const int b = i >> 20;
    const float* base = g_qkv + ((size_t)(b * SS + s)) * (3 * DD) + h * DH;

    const float ex = (float)(2 * j) / 64.0f;
    const float scale = 1.0f / powf(10000.0f, ex);
    const float ang = (float)s * scale;
    const float c = cosf(ang), sn = sinf(ang);

    const size_t ob = (((size_t)(b * HH + h)) * SS + s) * DH;
    float q1 = base[j], q2 = base[j + 32];
    g_q[ob + j]      = q1 * c - q2 * sn;
    g_q[ob + j + 32] = q2 * c + q1 * sn;
    float k1 = base[DD + j], k2 = base[DD + j + 32];
    g_k[ob + j]      = k1 * c - k2 * sn;
    g_k[ob + j + 32] = k2 * c + k1 * sn;
    g_v[ob + j]      = base[2 * DD + j];
    g_v[ob + j + 32] = base[2 * DD + j + 32];
}

// ---------------- bias transpose + mask --------------------------------------
// g_sc[b,h,q,k] = attn_bias[b,q,k,h] + (kv_mask[b,k] ? 0 : -inf)
// CTA = (k-block of 128, q, b). Read 2048 contiguous floats, write 16 rows of
// 128 coalesced floats. Padded smem kills the transpose bank conflicts.
__global__ __launch_bounds__(256) void biast_kernel(
    const float* __restrict__ bias, const void* __restrict__ mask)
{
    __shared__ float s[128 * 17];
    const int b = blockIdx.z, q = blockIdx.y, kb = blockIdx.x * 128;
    const float* src = bias + (((size_t)(b * SS + q)) * SS + kb) * HH;
    const int t = threadIdx.x;
#pragma unroll
    for (int i = 0; i < 2; i++) {
        const int idx = (t + i * 256) * 4;       // 0..2044
        float4 v = *(const float4*)(src + idx);
        const int kk = idx >> 4, hb = idx & 15;  // hb in {0,4,8,12}
        s[kk * 17 + hb + 0] = v.x;
        s[kk * 17 + hb + 1] = v.y;
        s[kk * 17 + hb + 2] = v.z;
        s[kk * 17 + hb + 3] = v.w;
    }
    __syncthreads();
    const int kind = g_mask_kind;
    const int hh = t >> 4;          // 0..15
    const int k0 = (t & 15) * 8;    // 0..120
    float* dst = g_sc + (((size_t)((b * HH + hh) * SS + q)) * SS) + kb + k0;
    const int midx = b * SS + kb + k0;
#pragma unroll
    for (int i = 0; i < 8; i++) {
        float val = s[(k0 + i) * 17 + hh];
        dst[i] = mask_at(mask, kind, midx + i) ? val : -INFINITY;
    }
}

// ---------------- scores: g_sc = Q @ K^T / 8 + g_sc (in place) ---------------
// Per (b,h): 128x128 tiles, 8x8 per thread, d-chunks of 16.
__global__ __launch_bounds__(256) void qk_kernel() {
    constexpr int BT = 128, BK = 16;
    __shared__ float Qs[BK][BT];
    __shared__ float Ks[BK][BT];
    const int bh = blockIdx.z;
    const float* Qg = g_q + (size_t)bh * SS * DH;
    const float* Kg = g_k + (size_t)bh * SS * DH;
    const int t = threadIdx.x;
    const int tx = t & 15, ty = t >> 4;
    const int qbase = blockIdx.y * BT, kbase = blockIdx.x * BT;

    float acc[8][8];
#pragma unroll
    for (int i = 0; i < 8; i++)
#pragma unroll
        for (int j = 0; j < 8; j++) acc[i][j] = 0.f;

    for (int d0 = 0; d0 < DH; d0 += BK) {
#pragma unroll
        for (int i = 0; i < 2; i++) {
            const int row = (t >> 2) + i * 64;
            const int c4 = (t & 3) * 4;
            float4 qv = *(const float4*)(Qg + (size_t)(qbase + row) * DH + d0 + c4);
            Qs[c4 + 0][row] = qv.x; Qs[c4 + 1][row] = qv.y;
            Qs[c4 + 2][row] = qv.z; Qs[c4 + 3][row] = qv.w;
            float4 kv = *(const float4*)(Kg + (size_t)(kbase + row) * DH + d0 + c4);
            Ks[c4 + 0][row] = kv.x; Ks[c4 + 1][row] = kv.y;
            Ks[c4 + 2][row] = kv.z; Ks[c4 + 3][row] = kv.w;
        }
        __syncthreads();
#pragma unroll
        for (int kk = 0; kk < BK; kk++) {
            float ar[8], br[8];
#pragma unroll
            for (int i = 0; i < 8; i++) ar[i] = Qs[kk][ty * 8 + i];
#pragma unroll
            for (int j = 0; j < 8; j++) br[j] = Ks[kk][tx * 8 + j];
#pragma unroll
            for (int i = 0; i < 8; i++)
#pragma unroll
                for (int j = 0; j < 8; j++) acc[i][j] += ar[i] * br[j];
        }
        __syncthreads();
    }
    const float scale = 0.125f;  // 1/sqrt(64)
#pragma unroll
    for (int i = 0; i < 8; i++) {
        float* Cp = g_sc + ((size_t)bh * SS + qbase + ty * 8 + i) * SS + kbase + tx * 8;
#pragma unroll
        for (int j = 0; j < 8; j += 4) {
            float4 prev = *(const float4*)(Cp + j);
            float4 o;
            o.x = acc[i][j + 0] * scale + prev.x;
            o.y = acc[i][j + 1] * scale + prev.y;
            o.z = acc[i][j + 2] * scale + prev.z;
            o.w = acc[i][j + 3] * scale + prev.w;
            *(float4*)(Cp + j) = o;
        }
    }
}

// ---------------- row softmax over k (in place) ------------------------------
__global__ __launch_bounds__(256) void softmax_kernel() {
    const size_t row = blockIdx.x;  // b*H*S rows
    float* p = g_sc + row * SS;
    const int t = threadIdx.x;
    __shared__ float red[8];

    float v[8];
    float m = -INFINITY;
#pragma unroll
    for (int i = 0; i < 8; i++) { v[i] = p[t + i * 256]; m = fmaxf(m, v[i]); }
#pragma unroll
    for (int o = 16; o > 0; o >>= 1) m = fmaxf(m, __shfl_xor_sync(0xFFFFFFFFu, m, o));
    if ((t & 31) == 0) red[t >> 5] = m;
    __syncthreads();
    float M = -INFINITY;
#pragma unroll
    for (int w = 0; w < 8; w++) M = fmaxf(M, red[w]);
    __syncthreads();

    float sum = 0.f;
#pragma unroll
    for (int i = 0; i < 8; i++) { v[i] = expf(v[i] - M); sum += v[i]; }
#pragma unroll
    for (int o = 16; o > 0; o >>= 1) sum += __shfl_xor_sync(0xFFFFFFFFu, sum, o);
    if ((t & 31) == 0) red[t >> 5] = sum;
    __syncthreads();
    float tot = 0.f;
#pragma unroll
    for (int w = 0; w < 8; w++) tot += red[w];
    const float inv = 1.0f / tot;
#pragma unroll
    for (int i = 0; i < 8; i++) p[t + i * 256] = v[i] * inv;
}

// ---------------- PV: a_out[b, q, h*64+d] = attn[b,h,q,:] @ V[b,h,:,d] -------
// Per (q-tile 128, bh): BN = DH = 64, BK = 32; 8x4 per thread.
__global__ __launch_bounds__(256) void pv_kernel() {
    constexpr int BK = 32;
    __shared__ float Ps[BK][129];      // transposed attn tile, padded
    __shared__ float Vs[BK][DH];
    const int bh = blockIdx.y;
    const int b = bh >> 4, h = bh & 15;
    const float* Pg = g_sc + (size_t)bh * SS * SS;
    const float* Vg = g_v + (size_t)bh * SS * DH;
    const int t = threadIdx.x, tx = t & 15, ty = t >> 4;
    const int qbase = blockIdx.x * 128;

    float acc[8][4];
#pragma unroll
    for (int i = 0; i < 8; i++)
#pragma unroll
        for (int j = 0; j < 4; j++) acc[i][j] = 0.f;

    for (int k0 = 0; k0 < SS; k0 += BK) {
#pragma unroll
        for (int i = 0; i < 4; i++) {
            const int row = (t >> 3) + i * 32;
            const int c4 = (t & 7) * 4;
            float4 pv = *(const float4*)(Pg + (size_t)(qbase + row) * SS + k0 + c4);
            Ps[c4 + 0][row] = pv.x; Ps[c4 + 1][row] = pv.y;
            Ps[c4 + 2][row] = pv.z; Ps[c4 + 3][row] = pv.w;
        }
#pragma unroll
        for (int i = 0; i < 2; i++) {
            const int row = (t >> 4) + i * 16;
            const int c4 = (t & 15) * 4;
            *(float4*)&Vs[row][c4] = *(const float4*)(Vg + (size_t)(k0 + row) * DH + c4);
        }
        __syncthreads();
#pragma unroll
        for (int kk = 0; kk < BK; kk++) {
            float ar[8], br[4];
#pragma unroll
            for (int i = 0; i < 8; i++) ar[i] = Ps[kk][ty * 8 + i];
            float4 bv = *(const float4*)&Vs[kk][tx * 4];
            br[0] = bv.x; br[1] = bv.y; br[2] = bv.z; br[3] = bv.w;
#pragma unroll
            for (int i = 0; i < 8; i++)
#pragma unroll
                for (int j = 0; j < 4; j++) acc[i][j] += ar[i] * br[j];
        }
        __syncthreads();
    }
#pragma unroll
    for (int i = 0; i < 8; i++) {
        const int q = qbase + ty * 8 + i;
        float4 o = make_float4(acc[i][0], acc[i][1], acc[i][2], acc[i][3]);
        *(float4*)(g_ao + ((size_t)(b * SS + q)) * DD + h * DH + tx * 4) = o;
    }
}

// ---------------- launch ------------------------------------------------------
extern "C" void kernel_launch(void* const* d_in, const int* in_sizes, int n_in,
                              void* d_out, int out_size) {
    const float* x    = (const float*)d_in[0];
    const void*  mask = d_in[1];
    const float* bias = (const float*)d_in[2];
    const float* Wqkv = (const float*)d_in[3];
    const float* bqkv = (const float*)d_in[4];
    const float* Wout = (const float*)d_in[5];
    const float* bout = (const float*)d_in[6];
    float* out = (float*)d_out;

    float *qkv = nullptr, *ao = nullptr;
    cudaGetSymbolAddress((void**)&qkv, g_qkv);
    cudaGetSymbolAddress((void**)&ao, g_ao);

    detect_mask_kind_kernel<<<1, 1>>>((const unsigned int*)mask);

    // qkv = x @ W_qkv + b_qkv      [4096,1024] x [1024,3072]
    sgemm_bias_kernel<<<dim3(24, 32), 256>>>(x, Wqkv, bqkv, qkv, BB * SS, 3 * DD, DD);

    // head split + RoPE
    rope_split_kernel<<<(BB * SS * HH * 32) / 256, 256>>>();

    // biasT + mask into scores buffer
    biast_kernel<<<dim3(SS / 128, SS, BB), 256>>>(bias, mask);

    // scores = QK^T/8 + biasT (in place)
    qk_kernel<<<dim3(SS / 128, SS / 128, BB * HH), 256>>>();

    // softmax over k
    softmax_kernel<<<BB * HH * SS, 256>>>();

    // a_out = attn @ V  (written in [B,S,D] layout)
    pv_kernel<<<dim3(SS / 128, BB * HH), 256>>>();

    // out = a_out @ W_out + b_out  [4096,1024] x [1024,1024]
    sgemm_bias_kernel<<<dim3(8, 32), 256>>>(ao, Wout, bout, out, BB * SS, DD, DD);
}

// round 2
// speedup vs baseline: 1.2953x; 1.2953x over previous
#include <cuda_runtime.h>
#include <cuda_bf16.h>
#include <math.h>
#include <stdint.h>

// Problem constants
#define BB 2
#define SS 2048
#define DD 1024
#define HH 16
#define DH 64

#define LOG2E 1.4426950408889634f

// ---------------- scratch (static device globals; no allocation) -------------
__device__ float g_qkv[BB * SS * 3 * DD];             // 50 MB
__device__ float g_q[BB * HH * SS * DH];              // 16 MB
__device__ float g_k[BB * HH * SS * DH];              // 16 MB
__device__ float g_v[BB * HH * SS * DH];              // 16 MB
__device__ float g_sc[(size_t)BB * HH * SS * SS];     // 536 MB (biasT with mask folded in)
__device__ float g_ao[BB * SS * DD];                  // 16 MB
__device__ int   g_mask_kind;                         // 0=u8, 1=i32, 2=f32

// ---------------- mask dtype detection ---------------------------------------
__global__ void detect_mask_kind_kernel(const unsigned int* __restrict__ m) {
    bool sawFloat = false, sawBig = false;
    for (int i = 0; i < 1024; i++) {
        unsigned int w = m[i];
        if (w == 0x3F800000u) sawFloat = true;
        else if (w > 1u) sawBig = true;
    }
    g_mask_kind = sawFloat ? 2 : (sawBig ? 0 : 1);
}

__device__ __forceinline__ bool mask_at(const void* mask, int kind, int idx) {
    if (kind == 0) return ((const unsigned char*)mask)[idx] != 0;
    if (kind == 1) return ((const int*)mask)[idx] != 0;
    return ((const float*)mask)[idx] != 0.0f;
}

// ---------------- generic SGEMM: C[M,N] = A[M,K] @ B[K,N] + bias[N] ----------
__global__ __launch_bounds__(256) void sgemm_bias_kernel(
    const float* __restrict__ A, const float* __restrict__ B,
    const float* __restrict__ bias, float* __restrict__ C,
    int M, int N, int K)
{
    constexpr int BM = 128, BN = 128, BK = 8;
    __shared__ float As[BK][BM];
    __shared__ float Bs[BK][BN];
    const int tid = threadIdx.x;
    const int tx = tid & 15, ty = tid >> 4;
    const int rowC0 = blockIdx.y * BM + ty * 8;
    const int colC0 = blockIdx.x * BN + tx * 8;

    float acc[8][8];
#pragma unroll
    for (int i = 0; i < 8; i++)
#pragma unroll
        for (int j = 0; j < 8; j++) acc[i][j] = 0.f;

    const int aRow = tid >> 1, aCol = (tid & 1) * 4;
    const int bRow = tid >> 5, bCol = (tid & 31) * 4;
    const float* Ag = A + ((size_t)blockIdx.y * BM + aRow) * K + aCol;
    const float* Bg = B + (size_t)bRow * N + blockIdx.x * BN + bCol;

    for (int k0 = 0; k0 < K; k0 += BK) {
        float4 av = *(const float4*)(Ag + k0);
        As[aCol + 0][aRow] = av.x; As[aCol + 1][aRow] = av.y;
        As[aCol + 2][aRow] = av.z; As[aCol + 3][aRow] = av.w;
        float4 bv = *(const float4*)(Bg + (size_t)k0 * N);
        *(float4*)&Bs[bRow][bCol] = bv;
        __syncthreads();
#pragma unroll
        for (int kk = 0; kk < BK; kk++) {
            float ar[8], br[8];
#pragma unroll
            for (int i = 0; i < 8; i++) ar[i] = As[kk][ty * 8 + i];
            float4 b0 = *(const float4*)&Bs[kk][tx * 8];
            float4 b1 = *(const float4*)&Bs[kk][tx * 8 + 4];
            br[0] = b0.x; br[1] = b0.y; br[2] = b0.z; br[3] = b0.w;
            br[4] = b1.x; br[5] = b1.y; br[6] = b1.z; br[7] = b1.w;
#pragma unroll
            for (int i = 0; i < 8; i++)
#pragma unroll
                for (int j = 0; j < 8; j++) acc[i][j] += ar[i] * br[j];
        }
        __syncthreads();
    }
#pragma unroll
    for (int i = 0; i < 8; i++) {
        const int r = rowC0 + i;
#pragma unroll
        for (int j = 0; j < 8; j += 4) {
            const int c = colC0 + j;
            float4 o;
            o.x = acc[i][j + 0] + bias[c + 0];
            o.y = acc[i][j + 1] + bias[c + 1];
            o.z = acc[i][j + 2] + bias[c + 2];
            o.w = acc[i][j + 3] + bias[c + 3];
            *(float4*)(C + (size_t)r * N + c) = o;
        }
    }
}

// ---------------- RoPE + head split ------------------------------------------
__global__ __launch_bounds__(256) void rope_split_kernel() {
    const int i = blockIdx.x * 256 + threadIdx.x;
    const int j = i & 31;
    const int h = (i >> 5) & 15;
    const int s = (i >> 9) & 2047;
    const int b = i >> 20;
    const float* base = g_qkv + ((size_t)(b * SS + s)) * (3 * DD) + h * DH;

    const float ex = (float)(2 * j) / 64.0f;
    const float scale = 1.0f / powf(10000.0f, ex);
    const float ang = (float)s * scale;
    const float c = cosf(ang), sn = sinf(ang);

    const size_t ob = (((size_t)(b * HH + h)) * SS + s) * DH;
    float q1 = base[j], q2 = base[j + 32];
    g_q[ob + j]      = q1 * c - q2 * sn;
    g_q[ob + j + 32] = q2 * c + q1 * sn;
    float k1 = base[DD + j], k2 = base[DD + j + 32];
    g_k[ob + j]      = k1 * c - k2 * sn;
    g_k[ob + j + 32] = k2 * c + k1 * sn;
    g_v[ob + j]      = base[2 * DD + j];
    g_v[ob + j + 32] = base[2 * DD + j + 32];
}

// ---------------- bias transpose + mask --------------------------------------
__global__ __launch_bounds__(256) void biast_kernel(
    const float* __restrict__ bias, const void* __restrict__ mask)
{
    __shared__ float s[128 * 17];
    const int b = blockIdx.z, q = blockIdx.y, kb = blockIdx.x * 128;
    const float* src = bias + (((size_t)(b * SS + q)) * SS + kb) * HH;
    const int t = threadIdx.x;
#pragma unroll
    for (int i = 0; i < 2; i++) {
        const int idx = (t + i * 256) * 4;
        float4 v = *(const float4*)(src + idx);
        const int kk = idx >> 4, hb = idx & 15;
        s[kk * 17 + hb + 0] = v.x;
        s[kk * 17 + hb + 1] = v.y;
        s[kk * 17 + hb + 2] = v.z;
        s[kk * 17 + hb + 3] = v.w;
    }
    __syncthreads();
    const int kind = g_mask_kind;
    const int hh = t >> 4;
    const int k0 = (t & 15) * 8;
    float* dst = g_sc + (((size_t)((b * HH + hh) * SS + q)) * SS) + kb + k0;
    const int midx = b * SS + kb + k0;
#pragma unroll
    for (int i = 0; i < 8; i++) {
        float val = s[(k0 + i) * 17 + hh];
        dst[i] = mask_at(mask, kind, midx + i) ? val : -INFINITY;
    }
}

// ---------------- bf16-split helpers -----------------------------------------
__device__ __forceinline__ void split1(float x, __nv_bfloat16& h, __nv_bfloat16& l) {
    h = __float2bfloat16_rn(x);
    l = __float2bfloat16_rn(x - __bfloat162float(h));
}

__device__ __forceinline__ void splitpack(float x, float y, uint32_t& hi, uint32_t& lo) {
    __nv_bfloat16 hx, lx, hy, ly;
    split1(x, hx, lx);
    split1(y, hy, ly);
    __nv_bfloat162 H = __halves2bfloat162(hx, hy);
    __nv_bfloat162 L = __halves2bfloat162(lx, ly);
    hi = *reinterpret_cast<uint32_t*>(&H);
    lo = *reinterpret_cast<uint32_t*>(&L);
}

__device__ __forceinline__ void mma_bf16(float c[4], const uint32_t a[4],
                                         uint32_t b0, uint32_t b1) {
    asm volatile(
        "mma.sync.aligned.m16n8k16.row.col.f32.bf16.bf16.f32 "
        "{%0,%1,%2,%3}, {%4,%5,%6,%7}, {%8,%9}, {%0,%1,%2,%3};"
        : "+f"(c[0]), "+f"(c[1]), "+f"(c[2]), "+f"(c[3])
        : "r"(a[0]), "r"(a[1]), "r"(a[2]), "r"(a[3]), "r"(b0), "r"(b1));
}

__device__ __forceinline__ void ldsm_x2_trans(uint32_t& r0, uint32_t& r1, const void* p) {
    uint32_t a = (uint32_t)__cvta_generic_to_shared(p);
    asm volatile("ldmatrix.sync.aligned.m8n8.x2.trans.shared.b16 {%0,%1}, [%2];"
                 : "=r"(r0), "=r"(r1) : "r"(a));
}

// ---------------- fused flash attention --------------------------------------
// Grid: (SS/128, B*H). CTA: 256 threads = 8 warps, each warp owns 16 q-rows.
// k-tiles of 64. Scores = (Q/8) @ K^T + biasT (bias is the accumulator init,
// includes -inf mask). Online softmax, O accumulated in fp32 registers.
// All MMA work is bf16 2-term split with 3 passes (hi*hi + hi*lo + lo*hi).
__global__ __launch_bounds__(256) void flash_kernel() {
    __shared__ __align__(16) __nv_bfloat16 sKh[64][72];
    __shared__ __align__(16) __nv_bfloat16 sKl[64][72];
    __shared__ __align__(16) __nv_bfloat16 sVh[64][72];
    __shared__ __align__(16) __nv_bfloat16 sVl[64][72];

    const int bh = blockIdx.y;
    const int b = bh >> 4, h = bh & 15;
    const int q0 = blockIdx.x * 128;
    const int t = threadIdx.x;
    const int w = t >> 5, lane = t & 31;
    const int l4 = lane >> 2, lm4 = lane & 3;

    const float* Qg = g_q + (size_t)bh * SS * DH;
    const float* Kg = g_k + (size_t)bh * SS * DH;
    const float* Vg = g_v + (size_t)bh * SS * DH;
    const float* Bt = g_sc + (size_t)bh * SS * SS;

    const int qrow = q0 + w * 16 + l4;   // rows qrow and qrow+8 per lane

    // ---- load Q fragments once (scaled by 1/8, hi/lo bf16 split) ----
    uint32_t aQh[4][4], aQl[4][4];
#pragma unroll
    for (int kc = 0; kc < 4; kc++) {
        const int c0 = kc * 16 + 2 * lm4;
        float2 x0 = *(const float2*)&Qg[(size_t)qrow * DH + c0];
        float2 x1 = *(const float2*)&Qg[(size_t)(qrow + 8) * DH + c0];
        float2 x2 = *(const float2*)&Qg[(size_t)qrow * DH + c0 + 8];
        float2 x3 = *(const float2*)&Qg[(size_t)(qrow + 8) * DH + c0 + 8];
        splitpack(x0.x * 0.125f, x0.y * 0.125f, aQh[kc][0], aQl[kc][0]);
        splitpack(x1.x * 0.125f, x1.y * 0.125f, aQh[kc][1], aQl[kc][1]);
        splitpack(x2.x * 0.125f, x2.y * 0.125f, aQh[kc][2], aQl[kc][2]);
        splitpack(x3.x * 0.125f, x3.y * 0.125f, aQh[kc][3], aQl[kc][3]);
    }

    float m0 = -INFINITY, m1 = -INFINITY;
    float l0 = 0.f, l1 = 0.f;
    float O[8][4];
#pragma unroll
    for (int nt = 0; nt < 8; nt++)
#pragma unroll
        for (int j = 0; j < 4; j++) O[nt][j] = 0.f;

    for (int k0 = 0; k0 < SS; k0 += 64) {
        // ---- cooperative load + hi/lo split of K and V tiles ----
#pragma unroll
        for (int p = 0; p < 4; p++) {
            const int r = (t >> 4) + p * 16;
            const int c = (t & 15) * 4;
            float4 kv = *(const float4*)&Kg[(size_t)(k0 + r) * DH + c];
            float4 vv = *(const float4*)&Vg[(size_t)(k0 + r) * DH + c];
            __nv_bfloat16 hh, ll;
            split1(kv.x, hh, ll); sKh[r][c + 0] = hh; sKl[r][c + 0] = ll;
            split1(kv.y, hh, ll); sKh[r][c + 1] = hh; sKl[r][c + 1] = ll;
            split1(kv.z, hh, ll); sKh[r][c + 2] = hh; sKl[r][c + 2] = ll;
            split1(kv.w, hh, ll); sKh[r][c + 3] = hh; sKl[r][c + 3] = ll;
            split1(vv.x, hh, ll); sVh[r][c + 0] = hh; sVl[r][c + 0] = ll;
            split1(vv.y, hh, ll); sVh[r][c + 1] = hh; sVl[r][c + 1] = ll;
            split1(vv.z, hh, ll); sVh[r][c + 2] = hh; sVl[r][c + 2] = ll;
            split1(vv.w, hh, ll); sVh[r][c + 3] = hh; sVl[r][c + 3] = ll;
        }
        __syncthreads();

        // ---- S = bias; S += (Q/8) @ K^T (3-pass split) ----
        float c_[8][4];
#pragma unroll
        for (int nt = 0; nt < 8; nt++) {
            const int kc0 = k0 + nt * 8 + 2 * lm4;
            float2 b01 = *(const float2*)&Bt[(size_t)qrow * SS + kc0];
            float2 b23 = *(const float2*)&Bt[(size_t)(qrow + 8) * SS + kc0];
            c_[nt][0] = b01.x; c_[nt][1] = b01.y;
            c_[nt][2] = b23.x; c_[nt][3] = b23.y;
        }
#pragma unroll
        for (int nt = 0; nt < 8; nt++) {
#pragma unroll
            for (int kc = 0; kc < 4; kc++) {
                const int kr = nt * 8 + l4;
                const int dc = kc * 16 + 2 * lm4;
                uint32_t bh0 = *(const uint32_t*)&sKh[kr][dc];
                uint32_t bh1 = *(const uint32_t*)&sKh[kr][dc + 8];
                uint32_t bl0 = *(const uint32_t*)&sKl[kr][dc];
                uint32_t bl1 = *(const uint32_t*)&sKl[kr][dc + 8];
                mma_bf16(c_[nt], aQh[kc], bh0, bh1);
                mma_bf16(c_[nt], aQh[kc], bl0, bl1);
                mma_bf16(c_[nt], aQl[kc], bh0, bh1);
            }
        }

        // ---- online softmax ----
        float tm0 = -INFINITY, tm1 = -INFINITY;
#pragma unroll
        for (int nt = 0; nt < 8; nt++) {
            tm0 = fmaxf(tm0, fmaxf(c_[nt][0], c_[nt][1]));
            tm1 = fmaxf(tm1, fmaxf(c_[nt][2], c_[nt][3]));
        }
        tm0 = fmaxf(tm0, __shfl_xor_sync(0xFFFFFFFFu, tm0, 1));
        tm0 = fmaxf(tm0, __shfl_xor_sync(0xFFFFFFFFu, tm0, 2));
        tm1 = fmaxf(tm1, __shfl_xor_sync(0xFFFFFFFFu, tm1, 1));
        tm1 = fmaxf(tm1, __shfl_xor_sync(0xFFFFFFFFu, tm1, 2));

        const float nm0 = fmaxf(m0, tm0), nm1 = fmaxf(m1, tm1);
        const float sc0 = exp2f((m0 - nm0) * LOG2E);
        const float sc1 = exp2f((m1 - nm1) * LOG2E);
        m0 = nm0; m1 = nm1;

        float rs0 = 0.f, rs1 = 0.f;
#pragma unroll
        for (int nt = 0; nt < 8; nt++) {
            float p0 = exp2f((c_[nt][0] - m0) * LOG2E);
            float p1 = exp2f((c_[nt][1] - m0) * LOG2E);
            float p2 = exp2f((c_[nt][2] - m1) * LOG2E);
            float p3 = exp2f((c_[nt][3] - m1) * LOG2E);
            c_[nt][0] = p0; c_[nt][1] = p1; c_[nt][2] = p2; c_[nt][3] = p3;
            rs0 += p0 + p1; rs1 += p2 + p3;
        }
        rs0 += __shfl_xor_sync(0xFFFFFFFFu, rs0, 1);
        rs0 += __shfl_xor_sync(0xFFFFFFFFu, rs0, 2);
        rs1 += __shfl_xor_sync(0xFFFFFFFFu, rs1, 1);
        rs1 += __shfl_xor_sync(0xFFFFFFFFu, rs1, 2);
        l0 = l0 * sc0 + rs0;
        l1 = l1 * sc1 + rs1;

#pragma unroll
        for (int nt = 0; nt < 8; nt++) {
            O[nt][0] *= sc0; O[nt][1] *= sc0;
            O[nt][2] *= sc1; O[nt][3] *= sc1;
        }

        // ---- P fragments (bf16 hi/lo) ----
        uint32_t aPh[4][4], aPl[4][4];
#pragma unroll
        for (int kc = 0; kc < 4; kc++) {
            splitpack(c_[2 * kc][0],     c_[2 * kc][1],     aPh[kc][0], aPl[kc][0]);
            splitpack(c_[2 * kc][2],     c_[2 * kc][3],     aPh[kc][1], aPl[kc][1]);
            splitpack(c_[2 * kc + 1][0], c_[2 * kc + 1][1], aPh[kc][2], aPl[kc][2]);
            splitpack(c_[2 * kc + 1][2], c_[2 * kc + 1][3], aPh[kc][3], aPl[kc][3]);
        }

        // ---- O += P @ V (3-pass split), V frags via ldmatrix.trans ----
#pragma unroll
        for (int nt = 0; nt < 8; nt++) {
#pragma unroll
            for (int kc = 0; kc < 4; kc++) {
                const int vr = kc * 16 + (lane & 15);
                uint32_t bh0, bh1, bl0, bl1;
                ldsm_x2_trans(bh0, bh1, &sVh[vr][nt * 8]);
                ldsm_x2_trans(bl0, bl1, &sVl[vr][nt * 8]);
                mma_bf16(O[nt], aPh[kc], bh0, bh1);
                mma_bf16(O[nt], aPh[kc], bl0, bl1);
                mma_bf16(O[nt], aPl[kc], bh0, bh1);
            }
        }
        __syncthreads();
    }

    // ---- normalize and write [B,S,D] ----
    const float inv0 = 1.0f / l0, inv1 = 1.0f / l1;
#pragma unroll
    for (int nt = 0; nt < 8; nt++) {
        const int col = h * DH + nt * 8 + 2 * lm4;
        float2 o0 = make_float2(O[nt][0] * inv0, O[nt][1] * inv0);
        float2 o1 = make_float2(O[nt][2] * inv1, O[nt][3] * inv1);
        *(float2*)&g_ao[((size_t)(b * SS + qrow)) * DD + col] = o0;
        *(float2*)&g_ao[((size_t)(b * SS + qrow + 8)) * DD + col] = o1;
    }
}

// ---------------- launch ------------------------------------------------------
extern "C" void kernel_launch(void* const* d_in, const int* in_sizes, int n_in,
                              void* d_out, int out_size) {
    const float* x    = (const float*)d_in[0];
    const void*  mask = d_in[1];
    const float* bias = (const float*)d_in[2];
    const float* Wqkv = (const float*)d_in[3];
    const float* bqkv = (const float*)d_in[4];
    const float* Wout = (const float*)d_in[5];
    const float* bout = (const float*)d_in[6];
    float* out = (float*)d_out;

    float *qkv = nullptr, *ao = nullptr;
    cudaGetSymbolAddress((void**)&qkv, g_qkv);
    cudaGetSymbolAddress((void**)&ao, g_ao);

    detect_mask_kind_kernel<<<1, 1>>>((const unsigned int*)mask);

    // qkv = x @ W_qkv + b_qkv
    sgemm_bias_kernel<<<dim3(24, 32), 256>>>(x, Wqkv, bqkv, qkv, BB * SS, 3 * DD, DD);

    // head split + RoPE
    rope_split_kernel<<<(BB * SS * HH * 32) / 256, 256>>>();

    // biasT + mask into g_sc
    biast_kernel<<<dim3(SS / 128, SS, BB), 256>>>(bias, mask);

    // fused attention (QK^T + bias, softmax, @V) — bf16-split tensor cores
    flash_kernel<<<dim3(SS / 128, BB * HH), 256>>>();

    // out = a_out @ W_out + b_out
    sgemm_bias_kernel<<<dim3(8, 32), 256>>>(ao, Wout, bout, out, BB * SS, DD, DD);
}

// round 4
// speedup vs baseline: 1.8706x; 1.4441x over previous
#include <cuda_runtime.h>
#include <cuda_bf16.h>
#include <math.h>
#include <stdint.h>

// Problem constants
#define BB 2
#define SS 2048
#define DD 1024
#define HH 16
#define DH 64

#define LOG2E 1.4426950408889634f

// ---------------- scratch (static device globals; no allocation) -------------
__device__ float g_qkv[BB * SS * 3 * DD];                     // 50 MB
__device__ float g_q[BB * HH * SS * DH];                      // 16 MB
__device__ float g_k[BB * HH * SS * DH];                      // 16 MB
__device__ float g_v[BB * HH * SS * DH];                      // 16 MB
__device__ __nv_bfloat16 g_bt[(size_t)BB * HH * SS * SS];     // 268 MB (biasT+mask, bf16)
__device__ float g_ao[BB * SS * DD];                          // 16 MB
__device__ int   g_mask_kind;                                 // 0=u8, 1=i32, 2=f32

// ---------------- mask dtype detection ---------------------------------------
__global__ void detect_mask_kind_kernel(const unsigned int* __restrict__ m) {
    bool sawFloat = false, sawBig = false;
    for (int i = 0; i < 1024; i++) {
        unsigned int w = m[i];
        if (w == 0x3F800000u) sawFloat = true;
        else if (w > 1u) sawBig = true;
    }
    g_mask_kind = sawFloat ? 2 : (sawBig ? 0 : 1);
}

__device__ __forceinline__ bool mask_at(const void* mask, int kind, int idx) {
    if (kind == 0) return ((const unsigned char*)mask)[idx] != 0;
    if (kind == 1) return ((const int*)mask)[idx] != 0;
    return ((const float*)mask)[idx] != 0.0f;
}

// ---------------- bf16-split helpers -----------------------------------------
__device__ __forceinline__ void split1(float x, __nv_bfloat16& h, __nv_bfloat16& l) {
    h = __float2bfloat16_rn(x);
    l = __float2bfloat16_rn(x - __bfloat162float(h));
}

__device__ __forceinline__ void splitpack(float x, float y, uint32_t& hi, uint32_t& lo) {
    __nv_bfloat16 hx, lx, hy, ly;
    split1(x, hx, lx);
    split1(y, hy, ly);
    __nv_bfloat162 H = __halves2bfloat162(hx, hy);
    __nv_bfloat162 L = __halves2bfloat162(lx, ly);
    hi = *reinterpret_cast<uint32_t*>(&H);
    lo = *reinterpret_cast<uint32_t*>(&L);
}

__device__ __forceinline__ void mma_bf16(float c[4], const uint32_t a[4],
                                         uint32_t b0, uint32_t b1) {
    asm volatile(
        "mma.sync.aligned.m16n8k16.row.col.f32.bf16.bf16.f32 "
        "{%0,%1,%2,%3}, {%4,%5,%6,%7}, {%8,%9}, {%0,%1,%2,%3};"
        : "+f"(c[0]), "+f"(c[1]), "+f"(c[2]), "+f"(c[3])
        : "r"(a[0]), "r"(a[1]), "r"(a[2]), "r"(a[3]), "r"(b0), "r"(b1));
}

__device__ __forceinline__ void ldsm_x2_trans(uint32_t& r0, uint32_t& r1, const void* p) {
    uint32_t a = (uint32_t)__cvta_generic_to_shared(p);
    asm volatile("ldmatrix.sync.aligned.m8n8.x2.trans.shared.b16 {%0,%1}, [%2];"
                 : "=r"(r0), "=r"(r1) : "r"(a));
}

__device__ __forceinline__ void ldsm_x4(uint32_t& r0, uint32_t& r1, uint32_t& r2,
                                        uint32_t& r3, const void* p) {
    uint32_t a = (uint32_t)__cvta_generic_to_shared(p);
    asm volatile("ldmatrix.sync.aligned.m8n8.x4.shared.b16 {%0,%1,%2,%3}, [%4];"
                 : "=r"(r0), "=r"(r1), "=r"(r2), "=r"(r3) : "r"(a));
}

// ---------------- tensor-core GEMM: C = A[M,K] @ B[K,N] + bias[N] ------------
// bf16 2-term split, 3 MMA passes -> ~fp32 accuracy. 128x128 CTA tile, BK=32,
// 8 warps (2x4), warp tile 64x32. Register-prefetch software pipeline.
__global__ __launch_bounds__(256) void mma_gemm_bias_kernel(
    const float* __restrict__ A, const float* __restrict__ B,
    const float* __restrict__ bias, float* __restrict__ C,
    int M, int N, int K)
{
    __shared__ __align__(16) __nv_bfloat16 Ah[128][40];
    __shared__ __align__(16) __nv_bfloat16 Al[128][40];
    __shared__ __align__(16) __nv_bfloat16 Bh[32][136];
    __shared__ __align__(16) __nv_bfloat16 Bl[32][136];

    const int t = threadIdx.x, w = t >> 5, lane = t & 31;
    const int wm = (w >> 2) * 64, wn = (w & 3) * 32;
    const int row0 = blockIdx.y * 128, col0 = blockIdx.x * 128;

    float acc[4][4][4];
#pragma unroll
    for (int mf = 0; mf < 4; mf++)
#pragma unroll
        for (int nf = 0; nf < 4; nf++)
#pragma unroll
            for (int r = 0; r < 4; r++) acc[mf][nf][r] = 0.f;

    const int ar = t >> 1, ac = (t & 1) * 16;
    const int br = t >> 3, bc = (t & 7) * 16;
    const float* Ag = A + (size_t)(row0 + ar) * K + ac;
    const float* Bg = B + (size_t)br * N + col0 + bc;

    float4 ra[4], rb[4];
#pragma unroll
    for (int i = 0; i < 4; i++) ra[i] = *(const float4*)(Ag + i * 4);
#pragma unroll
    for (int i = 0; i < 4; i++) rb[i] = *(const float4*)(Bg + i * 4);

    for (int k0 = 0; k0 < K; k0 += 32) {
        // split current tile into smem
        {
            __nv_bfloat16 hb[16], lb[16];
            const float* f = (const float*)ra;
#pragma unroll
            for (int j = 0; j < 16; j++) split1(f[j], hb[j], lb[j]);
            *(uint4*)&Ah[ar][ac]     = *(uint4*)&hb[0];
            *(uint4*)&Ah[ar][ac + 8] = *(uint4*)&hb[8];
            *(uint4*)&Al[ar][ac]     = *(uint4*)&lb[0];
            *(uint4*)&Al[ar][ac + 8] = *(uint4*)&lb[8];
            f = (const float*)rb;
#pragma unroll
            for (int j = 0; j < 16; j++) split1(f[j], hb[j], lb[j]);
            *(uint4*)&Bh[br][bc]     = *(uint4*)&hb[0];
            *(uint4*)&Bh[br][bc + 8] = *(uint4*)&hb[8];
            *(uint4*)&Bl[br][bc]     = *(uint4*)&lb[0];
            *(uint4*)&Bl[br][bc + 8] = *(uint4*)&lb[8];
        }
        __syncthreads();

        // prefetch next tile into registers
        if (k0 + 32 < K) {
#pragma unroll
            for (int i = 0; i < 4; i++)
                ra[i] = *(const float4*)(Ag + (k0 + 32) + i * 4);
#pragma unroll
            for (int i = 0; i < 4; i++)
                rb[i] = *(const float4*)(Bg + (size_t)(k0 + 32) * N + i * 4);
        }

#pragma unroll
        for (int ks = 0; ks < 2; ks++) {
            const int kk = ks * 16;
            uint32_t a_h[4][4], a_l[4][4];
#pragma unroll
            for (int mf = 0; mf < 4; mf++) {
                const int r = wm + mf * 16 + (lane & 15);
                const int c = kk + (lane >> 4) * 8;
                ldsm_x4(a_h[mf][0], a_h[mf][1], a_h[mf][2], a_h[mf][3], &Ah[r][c]);
                ldsm_x4(a_l[mf][0], a_l[mf][1], a_l[mf][2], a_l[mf][3], &Al[r][c]);
            }
#pragma unroll
            for (int nf = 0; nf < 4; nf++) {
                const int krow = kk + (lane & 15);
                const int nc = wn + nf * 8;
                uint32_t bh0, bh1, bl0, bl1;
                ldsm_x2_trans(bh0, bh1, &Bh[krow][nc]);
                ldsm_x2_trans(bl0, bl1, &Bl[krow][nc]);
#pragma unroll
                for (int mf = 0; mf < 4; mf++) {
                    mma_bf16(acc[mf][nf], a_h[mf], bh0, bh1);
                    mma_bf16(acc[mf][nf], a_h[mf], bl0, bl1);
                    mma_bf16(acc[mf][nf], a_l[mf], bh0, bh1);
                }
            }
        }
        __syncthreads();
    }

    // epilogue: +bias, write fp32
#pragma unroll
    for (int mf = 0; mf < 4; mf++) {
#pragma unroll
        for (int nf = 0; nf < 4; nf++) {
            const int r = row0 + wm + mf * 16 + (lane >> 2);
            const int c = col0 + wn + nf * 8 + (lane & 3) * 2;
            const float bx = bias[c], by = bias[c + 1];
            float2 o0 = make_float2(acc[mf][nf][0] + bx, acc[mf][nf][1] + by);
            float2 o1 = make_float2(acc[mf][nf][2] + bx, acc[mf][nf][3] + by);
            *(float2*)&C[(size_t)r * N + c] = o0;
            *(float2*)&C[(size_t)(r + 8) * N + c] = o1;
        }
    }
}

// ---------------- RoPE + head split ------------------------------------------
__global__ __launch_bounds__(256) void rope_split_kernel() {
    const int i = blockIdx.x * 256 + threadIdx.x;
    const int j = i & 31;
    const int h = (i >> 5) & 15;
    const int s = (i >> 9) & 2047;
    const int b = i >> 20;
    const float* base = g_qkv + ((size_t)(b * SS + s)) * (3 * DD) + h * DH;

    const float ex = (float)(2 * j) / 64.0f;
    const float scale = 1.0f / powf(10000.0f, ex);
    const float ang = (float)s * scale;
    const float c = cosf(ang), sn = sinf(ang);

    const size_t ob = (((size_t)(b * HH + h)) * SS + s) * DH;
    float q1 = base[j], q2 = base[j + 32];
    g_q[ob + j]      = q1 * c - q2 * sn;
    g_q[ob + j + 32] = q2 * c + q1 * sn;
    float k1 = base[DD + j], k2 = base[DD + j + 32];
    g_k[ob + j]      = k1 * c - k2 * sn;
    g_k[ob + j + 32] = k2 * c + k1 * sn;
    g_v[ob + j]      = base[2 * DD + j];
    g_v[ob + j + 32] = base[2 * DD + j + 32];
}

// ---------------- bias transpose + mask -> bf16 -------------------------------
// g_bt[b,h,q,k] = bf16( attn_bias[b,q,k,h] ) or -inf where kv_mask[b,k]==0.
// CTA = (k-block of 256, q, b): read 256k x 16h floats (16KB, float4-coalesced),
// transpose via smem [h][k] (pitch 260), write 16 bf16 per thread as 2 uint4.
__global__ __launch_bounds__(256) void biast2_kernel(
    const float* __restrict__ bias, const void* __restrict__ mask)
{
    __shared__ float s[16 * 260];
    const int b = blockIdx.z, q = blockIdx.y, kb = blockIdx.x * 256;
    const float* src = bias + (((size_t)(b * SS + q)) * SS + kb) * HH;
    const int t = threadIdx.x;

#pragma unroll
    for (int i = 0; i < 4; i++) {
        const int fi = i * 256 + t;           // float4 index, 0..1023
        float4 v = ((const float4*)src)[fi];
        const int k = fi >> 2;
        const int hg = (fi & 3) * 4;
        s[(hg + 0) * 260 + k] = v.x;
        s[(hg + 1) * 260 + k] = v.y;
        s[(hg + 2) * 260 + k] = v.z;
        s[(hg + 3) * 260 + k] = v.w;
    }
    __syncthreads();

    const int kind = g_mask_kind;
    const int h = t >> 4, km = t & 15;
    const int base = b * SS + kb + km * 16;
    __nv_bfloat16 tmp[16];
#pragma unroll
    for (int j4 = 0; j4 < 4; j4++) {
        float4 v = *(const float4*)&s[h * 260 + km * 16 + j4 * 4];
        tmp[j4 * 4 + 0] = mask_at(mask, kind, base + j4 * 4 + 0)
                          ? __float2bfloat16(v.x) : __float2bfloat16(-INFINITY);
        tmp[j4 * 4 + 1] = mask_at(mask, kind, base + j4 * 4 + 1)
                          ? __float2bfloat16(v.y) : __float2bfloat16(-INFINITY);
        tmp[j4 * 4 + 2] = mask_at(mask, kind, base + j4 * 4 + 2)
                          ? __float2bfloat16(v.z) : __float2bfloat16(-INFINITY);
        tmp[j4 * 4 + 3] = mask_at(mask, kind, base + j4 * 4 + 3)
                          ? __float2bfloat16(v.w) : __float2bfloat16(-INFINITY);
    }
    __nv_bfloat16* dst = g_bt + (((size_t)((b * HH + h) * SS + q)) * SS) + kb + km * 16;
    *(uint4*)dst       = *(uint4*)&tmp[0];
    *(uint4*)(dst + 8) = *(uint4*)&tmp[8];
}

// ---------------- fused flash attention --------------------------------------
__global__ __launch_bounds__(256) void flash_kernel() {
    __shared__ __align__(16) __nv_bfloat16 sKh[64][72];
    __shared__ __align__(16) __nv_bfloat16 sKl[64][72];
    __shared__ __align__(16) __nv_bfloat16 sVh[64][72];
    __shared__ __align__(16) __nv_bfloat16 sVl[64][72];

    const int bh = blockIdx.y;
    const int b = bh >> 4, h = bh & 15;
    const int q0 = blockIdx.x * 128;
    const int t = threadIdx.x;
    const int w = t >> 5, lane = t & 31;
    const int l4 = lane >> 2, lm4 = lane & 3;

    const float* Qg = g_q + (size_t)bh * SS * DH;
    const float* Kg = g_k + (size_t)bh * SS * DH;
    const float* Vg = g_v + (size_t)bh * SS * DH;
    const __nv_bfloat16* Bt = g_bt + (size_t)bh * SS * SS;

    const int qrow = q0 + w * 16 + l4;

    uint32_t aQh[4][4], aQl[4][4];
#pragma unroll
    for (int kc = 0; kc < 4; kc++) {
        const int c0 = kc * 16 + 2 * lm4;
        float2 x0 = *(const float2*)&Qg[(size_t)qrow * DH + c0];
        float2 x1 = *(const float2*)&Qg[(size_t)(qrow + 8) * DH + c0];
        float2 x2 = *(const float2*)&Qg[(size_t)qrow * DH + c0 + 8];
        float2 x3 = *(const float2*)&Qg[(size_t)(qrow + 8) * DH + c0 + 8];
        splitpack(x0.x * 0.125f, x0.y * 0.125f, aQh[kc][0], aQl[kc][0]);
        splitpack(x1.x * 0.125f, x1.y * 0.125f, aQh[kc][1], aQl[kc][1]);
        splitpack(x2.x * 0.125f, x2.y * 0.125f, aQh[kc][2], aQl[kc][2]);
        splitpack(x3.x * 0.125f, x3.y * 0.125f, aQh[kc][3], aQl[kc][3]);
    }

    float m0 = -INFINITY, m1 = -INFINITY;
    float l0 = 0.f, l1 = 0.f;
    float O[8][4];
#pragma unroll
    for (int nt = 0; nt < 8; nt++)
#pragma unroll
        for (int j = 0; j < 4; j++) O[nt][j] = 0.f;

    for (int k0 = 0; k0 < SS; k0 += 64) {
#pragma unroll
        for (int p = 0; p < 4; p++) {
            const int r = (t >> 4) + p * 16;
            const int c = (t & 15) * 4;
            float4 kv = *(const float4*)&Kg[(size_t)(k0 + r) * DH + c];
            float4 vv = *(const float4*)&Vg[(size_t)(k0 + r) * DH + c];
            __nv_bfloat16 hh, ll;
            split1(kv.x, hh, ll); sKh[r][c + 0] = hh; sKl[r][c + 0] = ll;
            split1(kv.y, hh, ll); sKh[r][c + 1] = hh; sKl[r][c + 1] = ll;
            split1(kv.z, hh, ll); sKh[r][c + 2] = hh; sKl[r][c + 2] = ll;
            split1(kv.w, hh, ll); sKh[r][c + 3] = hh; sKl[r][c + 3] = ll;
            split1(vv.x, hh, ll); sVh[r][c + 0] = hh; sVl[r][c + 0] = ll;
            split1(vv.y, hh, ll); sVh[r][c + 1] = hh; sVl[r][c + 1] = ll;
            split1(vv.z, hh, ll); sVh[r][c + 2] = hh; sVl[r][c + 2] = ll;
            split1(vv.w, hh, ll); sVh[r][c + 3] = hh; sVl[r][c + 3] = ll;
        }
        __syncthreads();

        float c_[8][4];
#pragma unroll
        for (int nt = 0; nt < 8; nt++) {
            const int kc0 = k0 + nt * 8 + 2 * lm4;
            __nv_bfloat162 b01 = *(const __nv_bfloat162*)&Bt[(size_t)qrow * SS + kc0];
            __nv_bfloat162 b23 = *(const __nv_bfloat162*)&Bt[(size_t)(qrow + 8) * SS + kc0];
            c_[nt][0] = __bfloat162float(b01.x); c_[nt][1] = __bfloat162float(b01.y);
            c_[nt][2] = __bfloat162float(b23.x); c_[nt][3] = __bfloat162float(b23.y);
        }
#pragma unroll
        for (int nt = 0; nt < 8; nt++) {
#pragma unroll
            for (int kc = 0; kc < 4; kc++) {
                const int kr = nt * 8 + l4;
                const int dc = kc * 16 + 2 * lm4;
                uint32_t bh0 = *(const uint32_t*)&sKh[kr][dc];
                uint32_t bh1 = *(const uint32_t*)&sKh[kr][dc + 8];
                uint32_t bl0 = *(const uint32_t*)&sKl[kr][dc];
                uint32_t bl1 = *(const uint32_t*)&sKl[kr][dc + 8];
                mma_bf16(c_[nt], aQh[kc], bh0, bh1);
                mma_bf16(c_[nt], aQh[kc], bl0, bl1);
                mma_bf16(c_[nt], aQl[kc], bh0, bh1);
            }
        }

        float tm0 = -INFINITY, tm1 = -INFINITY;
#pragma unroll
        for (int nt = 0; nt < 8; nt++) {
            tm0 = fmaxf(tm0, fmaxf(c_[nt][0], c_[nt][1]));
            tm1 = fmaxf(tm1, fmaxf(c_[nt][2], c_[nt][3]));
        }
        tm0 = fmaxf(tm0, __shfl_xor_sync(0xFFFFFFFFu, tm0, 1));
        tm0 = fmaxf(tm0, __shfl_xor_sync(0xFFFFFFFFu, tm0, 2));
        tm1 = fmaxf(tm1, __shfl_xor_sync(0xFFFFFFFFu, tm1, 1));
        tm1 = fmaxf(tm1, __shfl_xor_sync(0xFFFFFFFFu, tm1, 2));

        const float nm0 = fmaxf(m0, tm0), nm1 = fmaxf(m1, tm1);
        const float sc0 = exp2f((m0 - nm0) * LOG2E);
        const float sc1 = exp2f((m1 - nm1) * LOG2E);
        m0 = nm0; m1 = nm1;

        float rs0 = 0.f, rs1 = 0.f;
#pragma unroll
        for (int nt = 0; nt < 8; nt++) {
            float p0 = exp2f((c_[nt][0] - m0) * LOG2E);
            float p1 = exp2f((c_[nt][1] - m0) * LOG2E);
            float p2 = exp2f((c_[nt][2] - m1) * LOG2E);
            float p3 = exp2f((c_[nt][3] - m1) * LOG2E);
            c_[nt][0] = p0; c_[nt][1] = p1; c_[nt][2] = p2; c_[nt][3] = p3;
            rs0 += p0 + p1; rs1 += p2 + p3;
        }
        rs0 += __shfl_xor_sync(0xFFFFFFFFu, rs0, 1);
        rs0 += __shfl_xor_sync(0xFFFFFFFFu, rs0, 2);
        rs1 += __shfl_xor_sync(0xFFFFFFFFu, rs1, 1);
        rs1 += __shfl_xor_sync(0xFFFFFFFFu, rs1, 2);
        l0 = l0 * sc0 + rs0;
        l1 = l1 * sc1 + rs1;

#pragma unroll
        for (int nt = 0; nt < 8; nt++) {
            O[nt][0] *= sc0; O[nt][1] *= sc0;
            O[nt][2] *= sc1; O[nt][3] *= sc1;
        }

        uint32_t aPh[4][4], aPl[4][4];
#pragma unroll
        for (int kc = 0; kc < 4; kc++) {
            splitpack(c_[2 * kc][0],     c_[2 * kc][1],     aPh[kc][0], aPl[kc][0]);
            splitpack(c_[2 * kc][2],     c_[2 * kc][3],     aPh[kc][1], aPl[kc][1]);
            splitpack(c_[2 * kc + 1][0], c_[2 * kc + 1][1], aPh[kc][2], aPl[kc][2]);
            splitpack(c_[2 * kc + 1][2], c_[2 * kc + 1][3], aPh[kc][3], aPl[kc][3]);
        }

#pragma unroll
        for (int nt = 0; nt < 8; nt++) {
#pragma unroll
            for (int kc = 0; kc < 4; kc++) {
                const int vr = kc * 16 + (lane & 15);
                uint32_t bh0, bh1, bl0, bl1;
                ldsm_x2_trans(bh0, bh1, &sVh[vr][nt * 8]);
                ldsm_x2_trans(bl0, bl1, &sVl[vr][nt * 8]);
                mma_bf16(O[nt], aPh[kc], bh0, bh1);
                mma_bf16(O[nt], aPh[kc], bl0, bl1);
                mma_bf16(O[nt], aPl[kc], bh0, bh1);
            }
        }
        __syncthreads();
    }

    const float inv0 = 1.0f / l0, inv1 = 1.0f / l1;
#pragma unroll
    for (int nt = 0; nt < 8; nt++) {
        const int col = h * DH + nt * 8 + 2 * lm4;
        float2 o0 = make_float2(O[nt][0] * inv0, O[nt][1] * inv0);
        float2 o1 = make_float2(O[nt][2] * inv1, O[nt][3] * inv1);
        *(float2*)&g_ao[((size_t)(b * SS + qrow)) * DD + col] = o0;
        *(float2*)&g_ao[((size_t)(b * SS + qrow + 8)) * DD + col] = o1;
    }
}

// ---------------- launch ------------------------------------------------------
extern "C" void kernel_launch(void* const* d_in, const int* in_sizes, int n_in,
                              void* d_out, int out_size) {
    const float* x    = (const float*)d_in[0];
    const void*  mask = d_in[1];
    const float* bias = (const float*)d_in[2];
    const float* Wqkv = (const float*)d_in[3];
    const float* bqkv = (const float*)d_in[4];
    const float* Wout = (const float*)d_in[5];
    const float* bout = (const float*)d_in[6];
    float* out = (float*)d_out;

    float *qkv = nullptr, *ao = nullptr;
    cudaGetSymbolAddress((void**)&qkv, g_qkv);
    cudaGetSymbolAddress((void**)&ao, g_ao);

    detect_mask_kind_kernel<<<1, 1>>>((const unsigned int*)mask);

    // qkv = x @ W_qkv + b_qkv  (bf16-split tensor cores)
    mma_gemm_bias_kernel<<<dim3(24, 32), 256>>>(x, Wqkv, bqkv, qkv, BB * SS, 3 * DD, DD);

    // head split + RoPE
    rope_split_kernel<<<(BB * SS * HH * 32) / 256, 256>>>();

    // biasT + mask -> bf16
    biast2_kernel<<<dim3(SS / 256, SS, BB), 256>>>(bias, mask);

    // fused attention
    flash_kernel<<<dim3(SS / 128, BB * HH), 256>>>();

    // out = a_out @ W_out + b_out  (bf16-split tensor cores)
    mma_gemm_bias_kernel<<<dim3(8, 32), 256>>>(ao, Wout, bout, out, BB * SS, DD, DD);
}

// round 5
// speedup vs baseline: 2.2771x; 1.2173x over previous
#include <cuda_runtime.h>
#include <cuda_bf16.h>
#include <math.h>
#include <stdint.h>

// Problem constants
#define BB 2
#define SS 2048
#define DD 1024
#define HH 16
#define DH 64

#define LOG2E 1.4426950408889634f

// ---------------- scratch (static device globals; no allocation) -------------
__device__ float g_qkv[BB * SS * 3 * DD];                     // 50 MB
__device__ float g_qs[BB * HH * SS * DH];                     // 16 MB
__device__ __nv_bfloat16 g_kh[BB * HH * SS * DH];             // 8 MB
__device__ __nv_bfloat16 g_kl[BB * HH * SS * DH];             // 8 MB
__device__ __nv_bfloat16 g_vh[BB * HH * SS * DH];             // 8 MB
__device__ __nv_bfloat16 g_vl[BB * HH * SS * DH];             // 8 MB
__device__ __nv_bfloat16 g_bt[(size_t)BB * HH * SS * SS];     // 268 MB
__device__ float g_ao[BB * SS * DD];                          // 16 MB
__device__ int   g_mask_kind;                                 // 0=u8, 1=i32, 2=f32

// ---------------- mask dtype detection ---------------------------------------
__global__ void detect_mask_kind_kernel(const unsigned int* __restrict__ m) {
    bool sawFloat = false, sawBig = false;
    for (int i = 0; i < 1024; i++) {
        unsigned int w = m[i];
        if (w == 0x3F800000u) sawFloat = true;
        else if (w > 1u) sawBig = true;
    }
    g_mask_kind = sawFloat ? 2 : (sawBig ? 0 : 1);
}

__device__ __forceinline__ bool mask_at(const void* mask, int kind, int idx) {
    if (kind == 0) return ((const unsigned char*)mask)[idx] != 0;
    if (kind == 1) return ((const int*)mask)[idx] != 0;
    return ((const float*)mask)[idx] != 0.0f;
}

// ---------------- bf16-split helpers -----------------------------------------
__device__ __forceinline__ void split1(float x, __nv_bfloat16& h, __nv_bfloat16& l) {
    h = __float2bfloat16_rn(x);
    l = __float2bfloat16_rn(x - __bfloat162float(h));
}

__device__ __forceinline__ void splitpack(float x, float y, uint32_t& hi, uint32_t& lo) {
    __nv_bfloat16 hx, lx, hy, ly;
    split1(x, hx, lx);
    split1(y, hy, ly);
    __nv_bfloat162 H = __halves2bfloat162(hx, hy);
    __nv_bfloat162 L = __halves2bfloat162(lx, ly);
    hi = *reinterpret_cast<uint32_t*>(&H);
    lo = *reinterpret_cast<uint32_t*>(&L);
}

__device__ __forceinline__ void mma_bf16(float c[4], const uint32_t a[4],
                                         uint32_t b0, uint32_t b1) {
    asm volatile(
        "mma.sync.aligned.m16n8k16.row.col.f32.bf16.bf16.f32 "
        "{%0,%1,%2,%3}, {%4,%5,%6,%7}, {%8,%9}, {%0,%1,%2,%3};"
        : "+f"(c[0]), "+f"(c[1]), "+f"(c[2]), "+f"(c[3])
        : "r"(a[0]), "r"(a[1]), "r"(a[2]), "r"(a[3]), "r"(b0), "r"(b1));
}

__device__ __forceinline__ void ldsm_x2_trans(uint32_t& r0, uint32_t& r1, const void* p) {
    uint32_t a = (uint32_t)__cvta_generic_to_shared(p);
    asm volatile("ldmatrix.sync.aligned.m8n8.x2.trans.shared.b16 {%0,%1}, [%2];"
                 : "=r"(r0), "=r"(r1) : "r"(a));
}

__device__ __forceinline__ void ldsm_x4(uint32_t& r0, uint32_t& r1, uint32_t& r2,
                                        uint32_t& r3, const void* p) {
    uint32_t a = (uint32_t)__cvta_generic_to_shared(p);
    asm volatile("ldmatrix.sync.aligned.m8n8.x4.shared.b16 {%0,%1,%2,%3}, [%4];"
                 : "=r"(r0), "=r"(r1), "=r"(r2), "=r"(r3) : "r"(a));
}

#define CP_ASYNC16(dst_u32, src_ptr) \
    asm volatile("cp.async.ca.shared.global [%0], [%1], 16;" \
                 :: "r"(dst_u32), "l"(src_ptr))
#define CP_COMMIT() asm volatile("cp.async.commit_group;")
#define CP_WAIT(N)  asm volatile("cp.async.wait_group %0;" :: "n"(N))

// ---------------- tensor-core GEMM: C = A[M,K] @ B[K,N] + bias[N] ------------
__global__ __launch_bounds__(256) void mma_gemm_bias_kernel(
    const float* __restrict__ A, const float* __restrict__ B,
    const float* __restrict__ bias, float* __restrict__ C,
    int M, int N, int K)
{
    __shared__ __align__(16) __nv_bfloat16 Ah[128][40];
    __shared__ __align__(16) __nv_bfloat16 Al[128][40];
    __shared__ __align__(16) __nv_bfloat16 Bh[32][136];
    __shared__ __align__(16) __nv_bfloat16 Bl[32][136];

    const int t = threadIdx.x, w = t >> 5, lane = t & 31;
    const int wm = (w >> 2) * 64, wn = (w & 3) * 32;
    const int row0 = blockIdx.y * 128, col0 = blockIdx.x * 128;

    float acc[4][4][4];
#pragma unroll
    for (int mf = 0; mf < 4; mf++)
#pragma unroll
        for (int nf = 0; nf < 4; nf++)
#pragma unroll
            for (int r = 0; r < 4; r++) acc[mf][nf][r] = 0.f;

    const int ar = t >> 1, ac = (t & 1) * 16;
    const int br = t >> 3, bc = (t & 7) * 16;
    const float* Ag = A + (size_t)(row0 + ar) * K + ac;
    const float* Bg = B + (size_t)br * N + col0 + bc;

    float4 ra[4], rb[4];
#pragma unroll
    for (int i = 0; i < 4; i++) ra[i] = *(const float4*)(Ag + i * 4);
#pragma unroll
    for (int i = 0; i < 4; i++) rb[i] = *(const float4*)(Bg + i * 4);

    for (int k0 = 0; k0 < K; k0 += 32) {
        {
            __nv_bfloat16 hb[16], lb[16];
            const float* f = (const float*)ra;
#pragma unroll
            for (int j = 0; j < 16; j++) split1(f[j], hb[j], lb[j]);
            *(uint4*)&Ah[ar][ac]     = *(uint4*)&hb[0];
            *(uint4*)&Ah[ar][ac + 8] = *(uint4*)&hb[8];
            *(uint4*)&Al[ar][ac]     = *(uint4*)&lb[0];
            *(uint4*)&Al[ar][ac + 8] = *(uint4*)&lb[8];
            f = (const float*)rb;
#pragma unroll
            for (int j = 0; j < 16; j++) split1(f[j], hb[j], lb[j]);
            *(uint4*)&Bh[br][bc]     = *(uint4*)&hb[0];
            *(uint4*)&Bh[br][bc + 8] = *(uint4*)&hb[8];
            *(uint4*)&Bl[br][bc]     = *(uint4*)&lb[0];
            *(uint4*)&Bl[br][bc + 8] = *(uint4*)&lb[8];
        }
        __syncthreads();

        if (k0 + 32 < K) {
#pragma unroll
            for (int i = 0; i < 4; i++)
                ra[i] = *(const float4*)(Ag + (k0 + 32) + i * 4);
#pragma unroll
            for (int i = 0; i < 4; i++)
                rb[i] = *(const float4*)(Bg + (size_t)(k0 + 32) * N + i * 4);
        }

#pragma unroll
        for (int ks = 0; ks < 2; ks++) {
            const int kk = ks * 16;
            uint32_t a_h[4][4], a_l[4][4];
#pragma unroll
            for (int mf = 0; mf < 4; mf++) {
                const int r = wm + mf * 16 + (lane & 15);
                const int c = kk + (lane >> 4) * 8;
                ldsm_x4(a_h[mf][0], a_h[mf][1], a_h[mf][2], a_h[mf][3], &Ah[r][c]);
                ldsm_x4(a_l[mf][0], a_l[mf][1], a_l[mf][2], a_l[mf][3], &Al[r][c]);
            }
#pragma unroll
            for (int nf = 0; nf < 4; nf++) {
                const int krow = kk + (lane & 15);
                const int nc = wn + nf * 8;
                uint32_t bh0, bh1, bl0, bl1;
                ldsm_x2_trans(bh0, bh1, &Bh[krow][nc]);
                ldsm_x2_trans(bl0, bl1, &Bl[krow][nc]);
#pragma unroll
                for (int mf = 0; mf < 4; mf++) {
                    mma_bf16(acc[mf][nf], a_h[mf], bh0, bh1);
                    mma_bf16(acc[mf][nf], a_h[mf], bl0, bl1);
                    mma_bf16(acc[mf][nf], a_l[mf], bh0, bh1);
                }
            }
        }
        __syncthreads();
    }

#pragma unroll
    for (int mf = 0; mf < 4; mf++) {
#pragma unroll
        for (int nf = 0; nf < 4; nf++) {
            const int r = row0 + wm + mf * 16 + (lane >> 2);
            const int c = col0 + wn + nf * 8 + (lane & 3) * 2;
            const float bx = bias[c], by = bias[c + 1];
            float2 o0 = make_float2(acc[mf][nf][0] + bx, acc[mf][nf][1] + by);
            float2 o1 = make_float2(acc[mf][nf][2] + bx, acc[mf][nf][3] + by);
            *(float2*)&C[(size_t)r * N + c] = o0;
            *(float2*)&C[(size_t)(r + 8) * N + c] = o1;
        }
    }
}

// ---------------- RoPE + head split + hi/lo presplit -------------------------
__global__ __launch_bounds__(256) void rope_split_kernel() {
    const int i = blockIdx.x * 256 + threadIdx.x;
    const int j = i & 31;
    const int h = (i >> 5) & 15;
    const int s = (i >> 9) & 2047;
    const int b = i >> 20;
    const float* base = g_qkv + ((size_t)(b * SS + s)) * (3 * DD) + h * DH;

    const float ex = (float)(2 * j) / 64.0f;
    const float scale = 1.0f / powf(10000.0f, ex);
    const float ang = (float)s * scale;
    const float c = cosf(ang), sn = sinf(ang);

    const size_t ob = (((size_t)(b * HH + h)) * SS + s) * DH;
    float q1 = base[j], q2 = base[j + 32];
    g_qs[ob + j]      = q1 * c - q2 * sn;
    g_qs[ob + j + 32] = q2 * c + q1 * sn;

    __nv_bfloat16 hh, ll;
    float k1 = base[DD + j], k2 = base[DD + j + 32];
    split1(k1 * c - k2 * sn, hh, ll);
    g_kh[ob + j] = hh;      g_kl[ob + j] = ll;
    split1(k2 * c + k1 * sn, hh, ll);
    g_kh[ob + j + 32] = hh; g_kl[ob + j + 32] = ll;

    split1(base[2 * DD + j], hh, ll);
    g_vh[ob + j] = hh;      g_vl[ob + j] = ll;
    split1(base[2 * DD + j + 32], hh, ll);
    g_vh[ob + j + 32] = hh; g_vl[ob + j + 32] = ll;
}

// ---------------- bias transpose + mask -> bf16 (no smem) --------------------
// Thread <-> (b, q, k-pair). Read 32 contiguous floats (heads of k and k+1),
// transpose in registers, write one uint32 (2 bf16, adjacent k) per head plane.
// Warp-level: reads 4KB contiguous, each STG covers 128B contiguous per plane.
__global__ __launch_bounds__(256) void biast3_kernel(
    const float* __restrict__ bias, const void* __restrict__ mask)
{
    const int b = blockIdx.z, q = blockIdx.y;
    const int k0 = (blockIdx.x * 256 + threadIdx.x) * 2;
    const float* src = bias + (((size_t)(b * SS + q)) * SS + k0) * HH;
    const int kind = g_mask_kind;
    const bool m0 = mask_at(mask, kind, b * SS + k0);
    const bool m1 = mask_at(mask, kind, b * SS + k0 + 1);

    float f[32];
#pragma unroll
    for (int i = 0; i < 8; i++) *(float4*)&f[i * 4] = ((const float4*)src)[i];

    const __nv_bfloat16 NINF = __float2bfloat16(-INFINITY);
    const size_t outbase = ((size_t)b * HH * SS + q) * SS + k0;
#pragma unroll
    for (int h = 0; h < HH; h++) {
        __nv_bfloat162 pk;
        pk.x = m0 ? __float2bfloat16(f[h]) : NINF;
        pk.y = m1 ? __float2bfloat16(f[16 + h]) : NINF;
        *(__nv_bfloat162*)&g_bt[outbase + (size_t)h * SS * SS] = pk;
    }
}

// ---------------- fused flash attention (cp.async double-buffered) -----------
// Dynamic smem: Kh,Kl,Vh,Vl each [2][64][72] bf16 (9216B per buf, 73728 total).
#define TILE_BUF 9216
#define OFF_KH 0
#define OFF_KL 18432
#define OFF_VH 36864
#define OFF_VL 55296

__global__ __launch_bounds__(256) void flash_kernel() {
    extern __shared__ __align__(16) char sm[];
    const uint32_t smem_base = (uint32_t)__cvta_generic_to_shared(sm);

    const int bh = blockIdx.y;
    const int b = bh >> 4, h = bh & 15;
    const int q0 = blockIdx.x * 128;
    const int t = threadIdx.x;
    const int w = t >> 5, lane = t & 31;
    const int l4 = lane >> 2, lm4 = lane & 3;

    const float* Qg = g_qs + (size_t)bh * SS * DH;
    const __nv_bfloat16* Khg = g_kh + (size_t)bh * SS * DH;
    const __nv_bfloat16* Klg = g_kl + (size_t)bh * SS * DH;
    const __nv_bfloat16* Vhg = g_vh + (size_t)bh * SS * DH;
    const __nv_bfloat16* Vlg = g_vl + (size_t)bh * SS * DH;
    const __nv_bfloat16* Bt = g_bt + (size_t)bh * SS * SS;

    const int qrow = q0 + w * 16 + l4;

    // per-thread copy coords: 2 chunks of 16B per array per tile
    const int cr0 = t >> 3, cc0 = (t & 7) * 8;          // row, elem-col of chunk 0
    const int cr1 = (t + 256) >> 3, cc1 = cc0;          // chunk 1 (+32 rows)

#define COPY_TILE(kt, buf)                                                        \
    {                                                                             \
        const int kb = (kt) * 64;                                                 \
        uint32_t d0 = smem_base + (buf) * TILE_BUF + cr0 * 144 + cc0 * 2;         \
        uint32_t d1 = smem_base + (buf) * TILE_BUF + cr1 * 144 + cc1 * 2;         \
        CP_ASYNC16(d0 + OFF_KH, Khg + (size_t)(kb + cr0) * DH + cc0);             \
        CP_ASYNC16(d1 + OFF_KH, Khg + (size_t)(kb + cr1) * DH + cc1);             \
        CP_ASYNC16(d0 + OFF_KL, Klg + (size_t)(kb + cr0) * DH + cc0);             \
        CP_ASYNC16(d1 + OFF_KL, Klg + (size_t)(kb + cr1) * DH + cc1);             \
        CP_ASYNC16(d0 + OFF_VH, Vhg + (size_t)(kb + cr0) * DH + cc0);             \
        CP_ASYNC16(d1 + OFF_VH, Vhg + (size_t)(kb + cr1) * DH + cc1);             \
        CP_ASYNC16(d0 + OFF_VL, Vlg + (size_t)(kb + cr0) * DH + cc0);             \
        CP_ASYNC16(d1 + OFF_VL, Vlg + (size_t)(kb + cr1) * DH + cc1);             \
        CP_COMMIT();                                                              \
    }

    // ---- Q fragments (scaled 1/8, hi/lo split) ----
    uint32_t aQh[4][4], aQl[4][4];
#pragma unroll
    for (int kc = 0; kc < 4; kc++) {
        const int c0 = kc * 16 + 2 * lm4;
        float2 x0 = *(const float2*)&Qg[(size_t)qrow * DH + c0];
        float2 x1 = *(const float2*)&Qg[(size_t)(qrow + 8) * DH + c0];
        float2 x2 = *(const float2*)&Qg[(size_t)qrow * DH + c0 + 8];
        float2 x3 = *(const float2*)&Qg[(size_t)(qrow + 8) * DH + c0 + 8];
        splitpack(x0.x * 0.125f, x0.y * 0.125f, aQh[kc][0], aQl[kc][0]);
        splitpack(x1.x * 0.125f, x1.y * 0.125f, aQh[kc][1], aQl[kc][1]);
        splitpack(x2.x * 0.125f, x2.y * 0.125f, aQh[kc][2], aQl[kc][2]);
        splitpack(x3.x * 0.125f, x3.y * 0.125f, aQh[kc][3], aQl[kc][3]);
    }

    COPY_TILE(0, 0);

    float m0 = -INFINITY, m1 = -INFINITY;
    float l0 = 0.f, l1 = 0.f;
    float O[8][4];
#pragma unroll
    for (int nt = 0; nt < 8; nt++)
#pragma unroll
        for (int j = 0; j < 4; j++) O[nt][j] = 0.f;

    for (int kt = 0; kt < SS / 64; kt++) {
        const int buf = kt & 1;
        const int k0 = kt * 64;
        if (kt + 1 < SS / 64) {
            COPY_TILE(kt + 1, buf ^ 1);
            CP_WAIT(1);
        } else {
            CP_WAIT(0);
        }
        __syncthreads();

        const __nv_bfloat16* sKh = (const __nv_bfloat16*)(sm + OFF_KH) + buf * 4608;
        const __nv_bfloat16* sKl = (const __nv_bfloat16*)(sm + OFF_KL) + buf * 4608;
        const __nv_bfloat16* sVh = (const __nv_bfloat16*)(sm + OFF_VH) + buf * 4608;
        const __nv_bfloat16* sVl = (const __nv_bfloat16*)(sm + OFF_VL) + buf * 4608;

        // ---- S = bias; S += (Q/8) @ K^T ----
        float c_[8][4];
#pragma unroll
        for (int nt = 0; nt < 8; nt++) {
            const int kc0 = k0 + nt * 8 + 2 * lm4;
            __nv_bfloat162 b01 = *(const __nv_bfloat162*)&Bt[(size_t)qrow * SS + kc0];
            __nv_bfloat162 b23 = *(const __nv_bfloat162*)&Bt[(size_t)(qrow + 8) * SS + kc0];
            c_[nt][0] = __bfloat162float(b01.x); c_[nt][1] = __bfloat162float(b01.y);
            c_[nt][2] = __bfloat162float(b23.x); c_[nt][3] = __bfloat162float(b23.y);
        }
#pragma unroll
        for (int nt = 0; nt < 8; nt++) {
#pragma unroll
            for (int kc = 0; kc < 4; kc++) {
                const int kr = nt * 8 + l4;
                const int dc = kc * 16 + 2 * lm4;
                uint32_t bh0 = *(const uint32_t*)&sKh[kr * 72 + dc];
                uint32_t bh1 = *(const uint32_t*)&sKh[kr * 72 + dc + 8];
                uint32_t bl0 = *(const uint32_t*)&sKl[kr * 72 + dc];
                uint32_t bl1 = *(const uint32_t*)&sKl[kr * 72 + dc + 8];
                mma_bf16(c_[nt], aQh[kc], bh0, bh1);
                mma_bf16(c_[nt], aQh[kc], bl0, bl1);
                mma_bf16(c_[nt], aQl[kc], bh0, bh1);
            }
        }

        // ---- online softmax ----
        float tm0 = -INFINITY, tm1 = -INFINITY;
#pragma unroll
        for (int nt = 0; nt < 8; nt++) {
            tm0 = fmaxf(tm0, fmaxf(c_[nt][0], c_[nt][1]));
            tm1 = fmaxf(tm1, fmaxf(c_[nt][2], c_[nt][3]));
        }
        tm0 = fmaxf(tm0, __shfl_xor_sync(0xFFFFFFFFu, tm0, 1));
        tm0 = fmaxf(tm0, __shfl_xor_sync(0xFFFFFFFFu, tm0, 2));
        tm1 = fmaxf(tm1, __shfl_xor_sync(0xFFFFFFFFu, tm1, 1));
        tm1 = fmaxf(tm1, __shfl_xor_sync(0xFFFFFFFFu, tm1, 2));

        const float nm0 = fmaxf(m0, tm0), nm1 = fmaxf(m1, tm1);
        const float sc0 = exp2f((m0 - nm0) * LOG2E);
        const float sc1 = exp2f((m1 - nm1) * LOG2E);
        m0 = nm0; m1 = nm1;

        float rs0 = 0.f, rs1 = 0.f;
#pragma unroll
        for (int nt = 0; nt < 8; nt++) {
            float p0 = exp2f((c_[nt][0] - m0) * LOG2E);
            float p1 = exp2f((c_[nt][1] - m0) * LOG2E);
            float p2 = exp2f((c_[nt][2] - m1) * LOG2E);
            float p3 = exp2f((c_[nt][3] - m1) * LOG2E);
            c_[nt][0] = p0; c_[nt][1] = p1; c_[nt][2] = p2; c_[nt][3] = p3;
            rs0 += p0 + p1; rs1 += p2 + p3;
        }
        rs0 += __shfl_xor_sync(0xFFFFFFFFu, rs0, 1);
        rs0 += __shfl_xor_sync(0xFFFFFFFFu, rs0, 2);
        rs1 += __shfl_xor_sync(0xFFFFFFFFu, rs1, 1);
        rs1 += __shfl_xor_sync(0xFFFFFFFFu, rs1, 2);
        l0 = l0 * sc0 + rs0;
        l1 = l1 * sc1 + rs1;

#pragma unroll
        for (int nt = 0; nt < 8; nt++) {
            O[nt][0] *= sc0; O[nt][1] *= sc0;
            O[nt][2] *= sc1; O[nt][3] *= sc1;
        }

        uint32_t aPh[4][4], aPl[4][4];
#pragma unroll
        for (int kc = 0; kc < 4; kc++) {
            splitpack(c_[2 * kc][0],     c_[2 * kc][1],     aPh[kc][0], aPl[kc][0]);
            splitpack(c_[2 * kc][2],     c_[2 * kc][3],     aPh[kc][1], aPl[kc][1]);
            splitpack(c_[2 * kc + 1][0], c_[2 * kc + 1][1], aPh[kc][2], aPl[kc][2]);
            splitpack(c_[2 * kc + 1][2], c_[2 * kc + 1][3], aPh[kc][3], aPl[kc][3]);
        }

#pragma unroll
        for (int nt = 0; nt < 8; nt++) {
#pragma unroll
            for (int kc = 0; kc < 4; kc++) {
                const int vr = kc * 16 + (lane & 15);
                uint32_t bh0, bh1, bl0, bl1;
                ldsm_x2_trans(bh0, bh1, &sVh[vr * 72 + nt * 8]);
                ldsm_x2_trans(bl0, bl1, &sVl[vr * 72 + nt * 8]);
                mma_bf16(O[nt], aPh[kc], bh0, bh1);
                mma_bf16(O[nt], aPh[kc], bl0, bl1);
                mma_bf16(O[nt], aPl[kc], bh0, bh1);
            }
        }
        __syncthreads();
    }

    const float inv0 = 1.0f / l0, inv1 = 1.0f / l1;
#pragma unroll
    for (int nt = 0; nt < 8; nt++) {
        const int col = h * DH + nt * 8 + 2 * lm4;
        float2 o0 = make_float2(O[nt][0] * inv0, O[nt][1] * inv0);
        float2 o1 = make_float2(O[nt][2] * inv1, O[nt][3] * inv1);
        *(float2*)&g_ao[((size_t)(b * SS + qrow)) * DD + col] = o0;
        *(float2*)&g_ao[((size_t)(b * SS + qrow + 8)) * DD + col] = o1;
    }
}

// ---------------- launch ------------------------------------------------------
extern "C" void kernel_launch(void* const* d_in, const int* in_sizes, int n_in,
                              void* d_out, int out_size) {
    const float* x    = (const float*)d_in[0];
    const void*  mask = d_in[1];
    const float* bias = (const float*)d_in[2];
    const float* Wqkv = (const float*)d_in[3];
    const float* bqkv = (const float*)d_in[4];
    const float* Wout = (const float*)d_in[5];
    const float* bout = (const float*)d_in[6];
    float* out = (float*)d_out;

    float *qkv = nullptr, *ao = nullptr;
    cudaGetSymbolAddress((void**)&qkv, g_qkv);
    cudaGetSymbolAddress((void**)&ao, g_ao);

    static bool attr_set = false;
    if (!attr_set) {
        cudaFuncSetAttribute(flash_kernel,
                             cudaFuncAttributeMaxDynamicSharedMemorySize, 73728);
        attr_set = true;
    }

    detect_mask_kind_kernel<<<1, 1>>>((const unsigned int*)mask);

    // qkv = x @ W_qkv + b_qkv
    mma_gemm_bias_kernel<<<dim3(24, 32), 256>>>(x, Wqkv, bqkv, qkv, BB * SS, 3 * DD, DD);

    // head split + RoPE + hi/lo presplit of K,V
    rope_split_kernel<<<(BB * SS * HH * 32) / 256, 256>>>();

    // biasT + mask -> bf16 (register transpose, no smem)
    biast3_kernel<<<dim3(SS / 512, SS, BB), 256>>>(bias, mask);

    // fused attention
    flash_kernel<<<dim3(SS / 128, BB * HH), 256, 73728>>>();

    // out = a_out @ W_out + b_out
    mma_gemm_bias_kernel<<<dim3(8, 32), 256>>>(ao, Wout, bout, out, BB * SS, DD, DD);
}

// round 7
// speedup vs baseline: 2.4972x; 1.0966x over previous
#include <cuda_runtime.h>
#include <cuda_bf16.h>
#include <math.h>
#include <stdint.h>

// Problem constants
#define BB 2
#define SS 2048
#define DD 1024
#define HH 16
#define DH 64

#define LOG2E 1.4426950408889634f

// ---------------- scratch (static device globals; no allocation) -------------
__device__ float g_qkv[BB * SS * 3 * DD];                     // 50 MB
__device__ float g_qs[BB * HH * SS * DH];                     // 16 MB
__device__ __nv_bfloat16 g_kh[BB * HH * SS * DH];             // 8 MB
__device__ __nv_bfloat16 g_kl[BB * HH * SS * DH];             // 8 MB
__device__ __nv_bfloat16 g_vh[BB * HH * SS * DH];             // 8 MB
__device__ __nv_bfloat16 g_vl[BB * HH * SS * DH];             // 8 MB
__device__ __nv_bfloat16 g_bt[(size_t)BB * HH * SS * SS];     // 268 MB
__device__ float g_ao[BB * SS * DD];                          // 16 MB
__device__ int   g_mask_kind;                                 // 0=u8, 1=i32, 2=f32

// ---------------- mask dtype detection (parallel) -----------------------------
__global__ void detect_mask_kind_kernel(const unsigned int* __restrict__ m) {
    __shared__ int f[2];
    const int t = threadIdx.x;
    if (t < 2) f[t] = 0;
    __syncthreads();
    bool sawFloat = false, sawBig = false;
#pragma unroll
    for (int j = 0; j < 4; j++) {
        unsigned int w = m[t * 4 + j];
        if (w == 0x3F800000u) sawFloat = true;
        else if (w > 1u) sawBig = true;
    }
    if (sawFloat) atomicOr(&f[0], 1);
    if (sawBig)   atomicOr(&f[1], 1);
    __syncthreads();
    if (t == 0) g_mask_kind = f[0] ? 2 : (f[1] ? 0 : 1);
}

__device__ __forceinline__ bool mask_at(const void* mask, int kind, int idx) {
    if (kind == 0) return ((const unsigned char*)mask)[idx] != 0;
    if (kind == 1) return ((const int*)mask)[idx] != 0;
    return ((const float*)mask)[idx] != 0.0f;
}

// ---------------- bf16-split helpers -----------------------------------------
__device__ __forceinline__ void split1(float x, __nv_bfloat16& h, __nv_bfloat16& l) {
    h = __float2bfloat16_rn(x);
    l = __float2bfloat16_rn(x - __bfloat162float(h));
}

__device__ __forceinline__ void splitpack(float x, float y, uint32_t& hi, uint32_t& lo) {
    __nv_bfloat16 hx, lx, hy, ly;
    split1(x, hx, lx);
    split1(y, hy, ly);
    __nv_bfloat162 H = __halves2bfloat162(hx, hy);
    __nv_bfloat162 L = __halves2bfloat162(lx, ly);
    hi = *reinterpret_cast<uint32_t*>(&H);
    lo = *reinterpret_cast<uint32_t*>(&L);
}

__device__ __forceinline__ void mma_bf16(float c[4], const uint32_t a[4],
                                         uint32_t b0, uint32_t b1) {
    asm volatile(
        "mma.sync.aligned.m16n8k16.row.col.f32.bf16.bf16.f32 "
        "{%0,%1,%2,%3}, {%4,%5,%6,%7}, {%8,%9}, {%0,%1,%2,%3};"
        : "+f"(c[0]), "+f"(c[1]), "+f"(c[2]), "+f"(c[3])
        : "r"(a[0]), "r"(a[1]), "r"(a[2]), "r"(a[3]), "r"(b0), "r"(b1));
}

__device__ __forceinline__ void ldsm_x2_trans(uint32_t& r0, uint32_t& r1, const void* p) {
    uint32_t a = (uint32_t)__cvta_generic_to_shared(p);
    asm volatile("ldmatrix.sync.aligned.m8n8.x2.trans.shared.b16 {%0,%1}, [%2];"
                 : "=r"(r0), "=r"(r1) : "r"(a));
}

__device__ __forceinline__ void ldsm_x4(uint32_t& r0, uint32_t& r1, uint32_t& r2,
                                        uint32_t& r3, const void* p) {
    uint32_t a = (uint32_t)__cvta_generic_to_shared(p);
    asm volatile("ldmatrix.sync.aligned.m8n8.x4.shared.b16 {%0,%1,%2,%3}, [%4];"
                 : "=r"(r0), "=r"(r1), "=r"(r2), "=r"(r3) : "r"(a));
}

#define CP_ASYNC16(dst_u32, src_ptr) \
    asm volatile("cp.async.ca.shared.global [%0], [%1], 16;" \
                 :: "r"(dst_u32), "l"(src_ptr))
#define CP_COMMIT() asm volatile("cp.async.commit_group;")
#define CP_WAIT(N)  asm volatile("cp.async.wait_group %0;" :: "n"(N))

// ---------------- tensor-core GEMM: C = A[M,K] @ B[K,N] + bias[N] ------------
// bf16 2-term split, 3 MMA passes -> ~fp32 accuracy. 128x128 CTA tile, BK=32,
// 8 warps (2x4), warp tile 64x32. Register-prefetch software pipeline.
__global__ __launch_bounds__(256) void mma_gemm_bias_kernel(
    const float* __restrict__ A, const float* __restrict__ B,
    const float* __restrict__ bias, float* __restrict__ C,
    int M, int N, int K)
{
    __shared__ __align__(16) __nv_bfloat16 Ah[128][40];
    __shared__ __align__(16) __nv_bfloat16 Al[128][40];
    __shared__ __align__(16) __nv_bfloat16 Bh[32][136];
    __shared__ __align__(16) __nv_bfloat16 Bl[32][136];

    const int t = threadIdx.x, w = t >> 5, lane = t & 31;
    const int wm = (w >> 2) * 64, wn = (w & 3) * 32;
    const int row0 = blockIdx.y * 128, col0 = blockIdx.x * 128;

    float acc[4][4][4];
#pragma unroll
    for (int mf = 0; mf < 4; mf++)
#pragma unroll
        for (int nf = 0; nf < 4; nf++)
#pragma unroll
            for (int r = 0; r < 4; r++) acc[mf][nf][r] = 0.f;

    const int ar = t >> 1, ac = (t & 1) * 16;
    const int br = t >> 3, bc = (t & 7) * 16;
    const float* Ag = A + (size_t)(row0 + ar) * K + ac;
    const float* Bg = B + (size_t)br * N + col0 + bc;

    float4 ra[4], rb[4];
#pragma unroll
    for (int i = 0; i < 4; i++) ra[i] = *(const float4*)(Ag + i * 4);
#pragma unroll
    for (int i = 0; i < 4; i++) rb[i] = *(const float4*)(Bg + i * 4);

    for (int k0 = 0; k0 < K; k0 += 32) {
        {
            __nv_bfloat16 hb[16], lb[16];
            const float* f = (const float*)ra;
#pragma unroll
            for (int j = 0; j < 16; j++) split1(f[j], hb[j], lb[j]);
            *(uint4*)&Ah[ar][ac]     = *(uint4*)&hb[0];
            *(uint4*)&Ah[ar][ac + 8] = *(uint4*)&hb[8];
            *(uint4*)&Al[ar][ac]     = *(uint4*)&lb[0];
            *(uint4*)&Al[ar][ac + 8] = *(uint4*)&lb[8];
            f = (const float*)rb;
#pragma unroll
            for (int j = 0; j < 16; j++) split1(f[j], hb[j], lb[j]);
            *(uint4*)&Bh[br][bc]     = *(uint4*)&hb[0];
            *(uint4*)&Bh[br][bc + 8] = *(uint4*)&hb[8];
            *(uint4*)&Bl[br][bc]     = *(uint4*)&lb[0];
            *(uint4*)&Bl[br][bc + 8] = *(uint4*)&lb[8];
        }
        __syncthreads();

        if (k0 + 32 < K) {
#pragma unroll
            for (int i = 0; i < 4; i++)
                ra[i] = *(const float4*)(Ag + (k0 + 32) + i * 4);
#pragma unroll
            for (int i = 0; i < 4; i++)
                rb[i] = *(const float4*)(Bg + (size_t)(k0 + 32) * N + i * 4);
        }

#pragma unroll
        for (int ks = 0; ks < 2; ks++) {
            const int kk = ks * 16;
            uint32_t a_h[4][4], a_l[4][4];
#pragma unroll
            for (int mf = 0; mf < 4; mf++) {
                const int r = wm + mf * 16 + (lane & 15);
                const int c = kk + (lane >> 4) * 8;
                ldsm_x4(a_h[mf][0], a_h[mf][1], a_h[mf][2], a_h[mf][3], &Ah[r][c]);
                ldsm_x4(a_l[mf][0], a_l[mf][1], a_l[mf][2], a_l[mf][3], &Al[r][c]);
            }
#pragma unroll
            for (int nf = 0; nf < 4; nf++) {
                const int krow = kk + (lane & 15);
                const int nc = wn + nf * 8;
                uint32_t bh0, bh1, bl0, bl1;
                ldsm_x2_trans(bh0, bh1, &Bh[krow][nc]);
                ldsm_x2_trans(bl0, bl1, &Bl[krow][nc]);
#pragma unroll
                for (int mf = 0; mf < 4; mf++) {
                    mma_bf16(acc[mf][nf], a_h[mf], bh0, bh1);
                    mma_bf16(acc[mf][nf], a_h[mf], bl0, bl1);
                    mma_bf16(acc[mf][nf], a_l[mf], bh0, bh1);
                }
            }
        }
        __syncthreads();
    }

#pragma unroll
    for (int mf = 0; mf < 4; mf++) {
#pragma unroll
        for (int nf = 0; nf < 4; nf++) {
            const int r = row0 + wm + mf * 16 + (lane >> 2);
            const int c = col0 + wn + nf * 8 + (lane & 3) * 2;
            const float bx = bias[c], by = bias[c + 1];
            float2 o0 = make_float2(acc[mf][nf][0] + bx, acc[mf][nf][1] + by);
            float2 o1 = make_float2(acc[mf][nf][2] + bx, acc[mf][nf][3] + by);
            *(float2*)&C[(size_t)r * N + c] = o0;
            *(float2*)&C[(size_t)(r + 8) * N + c] = o1;
        }
    }
}

// ---------------- RoPE + head split + hi/lo presplit -------------------------
__global__ __launch_bounds__(256) void rope_split_kernel() {
    const int i = blockIdx.x * 256 + threadIdx.x;
    const int j = i & 31;
    const int h = (i >> 5) & 15;
    const int s = (i >> 9) & 2047;
    const int b = i >> 20;
    const float* base = g_qkv + ((size_t)(b * SS + s)) * (3 * DD) + h * DH;

    const float ex = (float)(2 * j) / 64.0f;
    const float scale = 1.0f / powf(10000.0f, ex);
    const float ang = (float)s * scale;
    const float c = cosf(ang), sn = sinf(ang);

    const size_t ob = (((size_t)(b * HH + h)) * SS + s) * DH;
    float q1 = base[j], q2 = base[j + 32];
    g_qs[ob + j]      = q1 * c - q2 * sn;
    g_qs[ob + j + 32] = q2 * c + q1 * sn;

    __nv_bfloat16 hh, ll;
    float k1 = base[DD + j], k2 = base[DD + j + 32];
    split1(k1 * c - k2 * sn, hh, ll);
    g_kh[ob + j] = hh;      g_kl[ob + j] = ll;
    split1(k2 * c + k1 * sn, hh, ll);
    g_kh[ob + j + 32] = hh; g_kl[ob + j + 32] = ll;

    split1(base[2 * DD + j], hh, ll);
    g_vh[ob + j] = hh;      g_vl[ob + j] = ll;
    split1(base[2 * DD + j + 32], hh, ll);
    g_vh[ob + j + 32] = hh; g_vl[ob + j + 32] = ll;
}

// ---------------- bias transpose + mask -> bf16 (no smem) --------------------
__global__ __launch_bounds__(256) void biast3_kernel(
    const float* __restrict__ bias, const void* __restrict__ mask)
{
    const int b = blockIdx.z, q = blockIdx.y;
    const int k0 = (blockIdx.x * 256 + threadIdx.x) * 2;
    const float* src = bias + (((size_t)(b * SS + q)) * SS + k0) * HH;
    const int kind = g_mask_kind;
    const bool m0 = mask_at(mask, kind, b * SS + k0);
    const bool m1 = mask_at(mask, kind, b * SS + k0 + 1);

    float f[32];
#pragma unroll
    for (int i = 0; i < 8; i++) *(float4*)&f[i * 4] = ((const float4*)src)[i];

    const __nv_bfloat16 NINF = __float2bfloat16(-INFINITY);
    const size_t outbase = ((size_t)b * HH * SS + q) * SS + k0;
#pragma unroll
    for (int h = 0; h < HH; h++) {
        __nv_bfloat162 pk;
        pk.x = m0 ? __float2bfloat16(f[h]) : NINF;
        pk.y = m1 ? __float2bfloat16(f[16 + h]) : NINF;
        *(__nv_bfloat162*)&g_bt[outbase + (size_t)h * SS * SS] = pk;
    }
}

// ---------------- fused flash attention --------------------------------------
// 128 threads (4 warps), q-tile 64 -> 2 CTAs/SM co-resident (regs+smem fit),
// so barrier/memory stalls of one CTA hide behind the other's MMA stream.
// k-tiles of 64, cp.async double-buffered.
#define TILE_BUF 9216
#define OFF_KH 0
#define OFF_KL 18432
#define OFF_VH 36864
#define OFF_VL 55296

__global__ __launch_bounds__(128) void flash_kernel() {
    extern __shared__ __align__(16) char sm[];
    const uint32_t smem_base = (uint32_t)__cvta_generic_to_shared(sm);

    const int bh = blockIdx.y;
    const int b = bh >> 4, h = bh & 15;
    const int q0 = blockIdx.x * 64;
    const int t = threadIdx.x;
    const int w = t >> 5, lane = t & 31;
    const int l4 = lane >> 2, lm4 = lane & 3;

    const float* Qg = g_qs + (size_t)bh * SS * DH;
    const __nv_bfloat16* Khg = g_kh + (size_t)bh * SS * DH;
    const __nv_bfloat16* Klg = g_kl + (size_t)bh * SS * DH;
    const __nv_bfloat16* Vhg = g_vh + (size_t)bh * SS * DH;
    const __nv_bfloat16* Vlg = g_vl + (size_t)bh * SS * DH;
    const __nv_bfloat16* Bt = g_bt + (size_t)bh * SS * SS;

    const int qrow = q0 + w * 16 + l4;

    // per-thread copy coords: 4 chunks of 16B per array per tile (128 threads)
    const int cr0 = t >> 3, cc = (t & 7) * 8;   // rows cr0, cr0+16, cr0+32, cr0+48

#define COPY_TILE(kt, buf)                                                          \
    {                                                                               \
        const int kb = (kt) * 64;                                                   \
        _Pragma("unroll")                                                           \
        for (int ii = 0; ii < 4; ii++) {                                            \
            const int r = cr0 + ii * 16;                                            \
            const uint32_t d = smem_base + (buf) * TILE_BUF + r * 144 + cc * 2;     \
            CP_ASYNC16(d + OFF_KH, Khg + (size_t)(kb + r) * DH + cc);               \
            CP_ASYNC16(d + OFF_KL, Klg + (size_t)(kb + r) * DH + cc);               \
            CP_ASYNC16(d + OFF_VH, Vhg + (size_t)(kb + r) * DH + cc);               \
            CP_ASYNC16(d + OFF_VL, Vlg + (size_t)(kb + r) * DH + cc);               \
        }                                                                           \
        CP_COMMIT();                                                                \
    }

    // ---- Q fragments (scaled 1/8, hi/lo split) ----
    uint32_t aQh[4][4], aQl[4][4];
#pragma unroll
    for (int kc = 0; kc < 4; kc++) {
        const int c0 = kc * 16 + 2 * lm4;
        float2 x0 = *(const float2*)&Qg[(size_t)qrow * DH + c0];
        float2 x1 = *(const float2*)&Qg[(size_t)(qrow + 8) * DH + c0];
        float2 x2 = *(const float2*)&Qg[(size_t)qrow * DH + c0 + 8];
        float2 x3 = *(const float2*)&Qg[(size_t)(qrow + 8) * DH + c0 + 8];
        splitpack(x0.x * 0.125f, x0.y * 0.125f, aQh[kc][0], aQl[kc][0]);
        splitpack(x1.x * 0.125f, x1.y * 0.125f, aQh[kc][1], aQl[kc][1]);
        splitpack(x2.x * 0.125f, x2.y * 0.125f, aQh[kc][2], aQl[kc][2]);
        splitpack(x3.x * 0.125f, x3.y * 0.125f, aQh[kc][3], aQl[kc][3]);
    }

    COPY_TILE(0, 0);

    float m0 = -INFINITY, m1 = -INFINITY;
    float l0 = 0.f, l1 = 0.f;
    float O[8][4];
#pragma unroll
    for (int nt = 0; nt < 8; nt++)
#pragma unroll
        for (int j = 0; j < 4; j++) O[nt][j] = 0.f;

    for (int kt = 0; kt < SS / 64; kt++) {
        const int buf = kt & 1;
        const int k0 = kt * 64;
        if (kt + 1 < SS / 64) {
            COPY_TILE(kt + 1, buf ^ 1);
            CP_WAIT(1);
        } else {
            CP_WAIT(0);
        }
        __syncthreads();

        const __nv_bfloat16* sKh = (const __nv_bfloat16*)(sm + OFF_KH) + buf * 4608;
        const __nv_bfloat16* sKl = (const __nv_bfloat16*)(sm + OFF_KL) + buf * 4608;
        const __nv_bfloat16* sVh = (const __nv_bfloat16*)(sm + OFF_VH) + buf * 4608;
        const __nv_bfloat16* sVl = (const __nv_bfloat16*)(sm + OFF_VL) + buf * 4608;

        // ---- S = bias; S += (Q/8) @ K^T ----
        float c_[8][4];
#pragma unroll
        for (int nt = 0; nt < 8; nt++) {
            const int kc0 = k0 + nt * 8 + 2 * lm4;
            __nv_bfloat162 b01 = *(const __nv_bfloat162*)&Bt[(size_t)qrow * SS + kc0];
            __nv_bfloat162 b23 = *(const __nv_bfloat162*)&Bt[(size_t)(qrow + 8) * SS + kc0];
            c_[nt][0] = __bfloat162float(b01.x); c_[nt][1] = __bfloat162float(b01.y);
            c_[nt][2] = __bfloat162float(b23.x); c_[nt][3] = __bfloat162float(b23.y);
        }
#pragma unroll
        for (int nt = 0; nt < 8; nt++) {
#pragma unroll
            for (int kc = 0; kc < 4; kc++) {
                const int kr = nt * 8 + l4;
                const int dc = kc * 16 + 2 * lm4;
                uint32_t bh0 = *(const uint32_t*)&sKh[kr * 72 + dc];
                uint32_t bh1 = *(const uint32_t*)&sKh[kr * 72 + dc + 8];
                uint32_t bl0 = *(const uint32_t*)&sKl[kr * 72 + dc];
                uint32_t bl1 = *(const uint32_t*)&sKl[kr * 72 + dc + 8];
                mma_bf16(c_[nt], aQh[kc], bh0, bh1);
                mma_bf16(c_[nt], aQh[kc], bl0, bl1);
                mma_bf16(c_[nt], aQl[kc], bh0, bh1);
            }
        }

        // ---- online softmax ----
        float tm0 = -INFINITY, tm1 = -INFINITY;
#pragma unroll
        for (int nt = 0; nt < 8; nt++) {
            tm0 = fmaxf(tm0, fmaxf(c_[nt][0], c_[nt][1]));
            tm1 = fmaxf(tm1, fmaxf(c_[nt][2], c_[nt][3]));
        }
        tm0 = fmaxf(tm0, __shfl_xor_sync(0xFFFFFFFFu, tm0, 1));
        tm0 = fmaxf(tm0, __shfl_xor_sync(0xFFFFFFFFu, tm0, 2));
        tm1 = fmaxf(tm1, __shfl_xor_sync(0xFFFFFFFFu, tm1, 1));
        tm1 = fmaxf(tm1, __shfl_xor_sync(0xFFFFFFFFu, tm1, 2));

        const float nm0 = fmaxf(m0, tm0), nm1 = fmaxf(m1, tm1);
        const float sc0 = exp2f((m0 - nm0) * LOG2E);
        const float sc1 = exp2f((m1 - nm1) * LOG2E);
        m0 = nm0; m1 = nm1;

        float rs0 = 0.f, rs1 = 0.f;
#pragma unroll
        for (int nt = 0; nt < 8; nt++) {
            float p0 = exp2f((c_[nt][0] - m0) * LOG2E);
            float p1 = exp2f((c_[nt][1] - m0) * LOG2E);
            float p2 = exp2f((c_[nt][2] - m1) * LOG2E);
            float p3 = exp2f((c_[nt][3] - m1) * LOG2E);
            c_[nt][0] = p0; c_[nt][1] = p1; c_[nt][2] = p2; c_[nt][3] = p3;
            rs0 += p0 + p1; rs1 += p2 + p3;
        }
        rs0 += __shfl_xor_sync(0xFFFFFFFFu, rs0, 1);
        rs0 += __shfl_xor_sync(0xFFFFFFFFu, rs0, 2);
        rs1 += __shfl_xor_sync(0xFFFFFFFFu, rs1, 1);
        rs1 += __shfl_xor_sync(0xFFFFFFFFu, rs1, 2);
        l0 = l0 * sc0 + rs0;
        l1 = l1 * sc1 + rs1;

#pragma unroll
        for (int nt = 0; nt < 8; nt++) {
            O[nt][0] *= sc0; O[nt][1] *= sc0;
            O[nt][2] *= sc1; O[nt][3] *= sc1;
        }

        // ---- P fragments (bf16 hi/lo) ----
        uint32_t aPh[4][4], aPl[4][4];
#pragma unroll
        for (int kc = 0; kc < 4; kc++) {
            splitpack(c_[2 * kc][0],     c_[2 * kc][1],     aPh[kc][0], aPl[kc][0]);
            splitpack(c_[2 * kc][2],     c_[2 * kc][3],     aPh[kc][1], aPl[kc][1]);
            splitpack(c_[2 * kc + 1][0], c_[2 * kc + 1][1], aPh[kc][2], aPl[kc][2]);
            splitpack(c_[2 * kc + 1][2], c_[2 * kc + 1][3], aPh[kc][3], aPl[kc][3]);
        }

        // ---- O += P @ V ----
#pragma unroll
        for (int nt = 0; nt < 8; nt++) {
#pragma unroll
            for (int kc = 0; kc < 4; kc++) {
                const int vr = kc * 16 + (lane & 15);
                uint32_t bh0, bh1, bl0, bl1;
                ldsm_x2_trans(bh0, bh1, &sVh[vr * 72 + nt * 8]);
                ldsm_x2_trans(bl0, bl1, &sVl[vr * 72 + nt * 8]);
                mma_bf16(O[nt], aPh[kc], bh0, bh1);
                mma_bf16(O[nt], aPh[kc], bl0, bl1);
                mma_bf16(O[nt], aPl[kc], bh0, bh1);
            }
        }
        __syncthreads();
    }

    const float inv0 = 1.0f / l0, inv1 = 1.0f / l1;
#pragma unroll
    for (int nt = 0; nt < 8; nt++) {
        const int col = h * DH + nt * 8 + 2 * lm4;
        float2 o0 = make_float2(O[nt][0] * inv0, O[nt][1] * inv0);
        float2 o1 = make_float2(O[nt][2] * inv1, O[nt][3] * inv1);
        *(float2*)&g_ao[((size_t)(b * SS + qrow)) * DD + col] = o0;
        *(float2*)&g_ao[((size_t)(b * SS + qrow + 8)) * DD + col] = o1;
    }
}

// ---------------- launch ------------------------------------------------------
extern "C" void kernel_launch(void* const* d_in, const int* in_sizes, int n_in,
                              void* d_out, int out_size) {
    const float* x    = (const float*)d_in[0];
    const void*  mask = d_in[1];
    const float* bias = (const float*)d_in[2];
    const float* Wqkv = (const float*)d_in[3];
    const float* bqkv = (const float*)d_in[4];
    const float* Wout = (const float*)d_in[5];
    const float* bout = (const float*)d_in[6];
    float* out = (float*)d_out;

    float *qkv = nullptr, *ao = nullptr;
    cudaGetSymbolAddress((void**)&qkv, g_qkv);
    cudaGetSymbolAddress((void**)&ao, g_ao);

    cudaFuncSetAttribute(flash_kernel,
                         cudaFuncAttributeMaxDynamicSharedMemorySize, 73728);

    detect_mask_kind_kernel<<<1, 256>>>((const unsigned int*)mask);

    // qkv = x @ W_qkv + b_qkv
    mma_gemm_bias_kernel<<<dim3(24, 32), 256>>>(x, Wqkv, bqkv, qkv, BB * SS, 3 * DD, DD);

    // head split + RoPE + hi/lo presplit of K,V
    rope_split_kernel<<<(BB * SS * HH * 32) / 256, 256>>>();

    // biasT + mask -> bf16 (register transpose, no smem)
    biast3_kernel<<<dim3(SS / 512, SS, BB), 256>>>(bias, mask);

    // fused attention (128-thread CTAs, q-tile 64 -> 2 CTAs/SM)
    flash_kernel<<<dim3(SS / 64, BB * HH), 128, 73728>>>();

    // out = a_out @ W_out + b_out
    mma_gemm_bias_kernel<<<dim3(8, 32), 256>>>(ao, Wout, bout, out, BB * SS, DD, DD);
}

// round 8
// speedup vs baseline: 2.6626x; 1.0663x over previous
#include <cuda_runtime.h>
#include <cuda_bf16.h>
#include <math.h>
#include <stdint.h>

// Problem constants
#define BB 2
#define SS 2048
#define DD 1024
#define HH 16
#define DH 64

#define LOG2E 1.4426950408889634f

// ---------------- scratch (static device globals; no allocation) -------------
__device__ float g_qkv[BB * SS * 3 * DD];                     // 50 MB
__device__ float g_qs[BB * HH * SS * DH];                     // 16 MB
__device__ __nv_bfloat16 g_kh[BB * HH * SS * DH];             // 8 MB
__device__ __nv_bfloat16 g_kl[BB * HH * SS * DH];             // 8 MB
__device__ __nv_bfloat16 g_vh[BB * HH * SS * DH];             // 8 MB
__device__ __nv_bfloat16 g_vl[BB * HH * SS * DH];             // 8 MB
__device__ __nv_bfloat16 g_bt[(size_t)BB * HH * SS * SS];     // 268 MB
__device__ float g_ao[BB * SS * DD];                          // 16 MB
__device__ int   g_mask_kind;                                 // 0=u8, 1=i32, 2=f32

// ---------------- mask dtype detection (parallel) -----------------------------
__global__ void detect_mask_kind_kernel(const unsigned int* __restrict__ m) {
    __shared__ int f[2];
    const int t = threadIdx.x;
    if (t < 2) f[t] = 0;
    __syncthreads();
    bool sawFloat = false, sawBig = false;
#pragma unroll
    for (int j = 0; j < 4; j++) {
        unsigned int w = m[t * 4 + j];
        if (w == 0x3F800000u) sawFloat = true;
        else if (w > 1u) sawBig = true;
    }
    if (sawFloat) atomicOr(&f[0], 1);
    if (sawBig)   atomicOr(&f[1], 1);
    __syncthreads();
    if (t == 0) g_mask_kind = f[0] ? 2 : (f[1] ? 0 : 1);
}

__device__ __forceinline__ bool mask_at(const void* mask, int kind, int idx) {
    if (kind == 0) return ((const unsigned char*)mask)[idx] != 0;
    if (kind == 1) return ((const int*)mask)[idx] != 0;
    return ((const float*)mask)[idx] != 0.0f;
}

// ---------------- bf16-split helpers -----------------------------------------
__device__ __forceinline__ void split1(float x, __nv_bfloat16& h, __nv_bfloat16& l) {
    h = __float2bfloat16_rn(x);
    l = __float2bfloat16_rn(x - __bfloat162float(h));
}

__device__ __forceinline__ void splitpack(float x, float y, uint32_t& hi, uint32_t& lo) {
    __nv_bfloat16 hx, lx, hy, ly;
    split1(x, hx, lx);
    split1(y, hy, ly);
    __nv_bfloat162 H = __halves2bfloat162(hx, hy);
    __nv_bfloat162 L = __halves2bfloat162(lx, ly);
    hi = *reinterpret_cast<uint32_t*>(&H);
    lo = *reinterpret_cast<uint32_t*>(&L);
}

__device__ __forceinline__ void mma_bf16(float c[4], const uint32_t a[4],
                                         uint32_t b0, uint32_t b1) {
    asm volatile(
        "mma.sync.aligned.m16n8k16.row.col.f32.bf16.bf16.f32 "
        "{%0,%1,%2,%3}, {%4,%5,%6,%7}, {%8,%9}, {%0,%1,%2,%3};"
        : "+f"(c[0]), "+f"(c[1]), "+f"(c[2]), "+f"(c[3])
        : "r"(a[0]), "r"(a[1]), "r"(a[2]), "r"(a[3]), "r"(b0), "r"(b1));
}

__device__ __forceinline__ void ldsm_x2_trans(uint32_t& r0, uint32_t& r1, const void* p) {
    uint32_t a = (uint32_t)__cvta_generic_to_shared(p);
    asm volatile("ldmatrix.sync.aligned.m8n8.x2.trans.shared.b16 {%0,%1}, [%2];"
                 : "=r"(r0), "=r"(r1) : "r"(a));
}

__device__ __forceinline__ void ldsm_x4(uint32_t& r0, uint32_t& r1, uint32_t& r2,
                                        uint32_t& r3, const void* p) {
    uint32_t a = (uint32_t)__cvta_generic_to_shared(p);
    asm volatile("ldmatrix.sync.aligned.m8n8.x4.shared.b16 {%0,%1,%2,%3}, [%4];"
                 : "=r"(r0), "=r"(r1), "=r"(r2), "=r"(r3) : "r"(a));
}

#define CP_ASYNC16(dst_u32, src_ptr) \
    asm volatile("cp.async.ca.shared.global [%0], [%1], 16;" \
                 :: "r"(dst_u32), "l"(src_ptr))
#define CP_COMMIT() asm volatile("cp.async.commit_group;")
#define CP_WAIT(N)  asm volatile("cp.async.wait_group %0;" :: "n"(N))

// ---------------- tensor-core GEMM: C = A[M,K] @ B[K,N] + bias[N] ------------
// 128 threads (4 warps, 2x2), CTA tile 64x128, warp tile 32x64, BK=32.
// ~150 regs/thread -> 3 CTAs/SM co-resident: latency hides across CTAs.
// bf16 2-term split, 3 MMA passes -> ~fp32 accuracy.
__global__ __launch_bounds__(128) void mma_gemm_bias_kernel(
    const float* __restrict__ A, const float* __restrict__ B,
    const float* __restrict__ bias, float* __restrict__ C,
    int M, int N, int K)
{
    __shared__ __align__(16) __nv_bfloat16 Ah[64][40];
    __shared__ __align__(16) __nv_bfloat16 Al[64][40];
    __shared__ __align__(16) __nv_bfloat16 Bh[32][136];
    __shared__ __align__(16) __nv_bfloat16 Bl[32][136];

    const int t = threadIdx.x, w = t >> 5, lane = t & 31;
    const int wm = (w & 1) * 32, wn = (w >> 1) * 64;
    const int row0 = blockIdx.y * 64, col0 = blockIdx.x * 128;

    float acc[2][8][4];
#pragma unroll
    for (int mf = 0; mf < 2; mf++)
#pragma unroll
        for (int nf = 0; nf < 8; nf++)
#pragma unroll
            for (int r = 0; r < 4; r++) acc[mf][nf][r] = 0.f;

    const int ar = t >> 1, ac = (t & 1) * 16;       // A: row, 16-float chunk
    const int br = t >> 4, bc = (t & 15) * 8;       // B: row-base, 8-float chunk
    const float* Ag = A + (size_t)(row0 + ar) * K + ac;
    const float* Bg = B + (size_t)br * N + col0 + bc;

    float4 ra[4], rb[8];
#pragma unroll
    for (int i = 0; i < 4; i++) ra[i] = *(const float4*)(Ag + i * 4);
#pragma unroll
    for (int rr = 0; rr < 4; rr++) {
        rb[rr * 2 + 0] = *(const float4*)(Bg + (size_t)(rr * 8) * N);
        rb[rr * 2 + 1] = *(const float4*)(Bg + (size_t)(rr * 8) * N + 4);
    }

    for (int k0 = 0; k0 < K; k0 += 32) {
        // split current tile into smem
        {
            __nv_bfloat16 hb[16], lb[16];
            const float* f = (const float*)ra;
#pragma unroll
            for (int j = 0; j < 16; j++) split1(f[j], hb[j], lb[j]);
            *(uint4*)&Ah[ar][ac]     = *(uint4*)&hb[0];
            *(uint4*)&Ah[ar][ac + 8] = *(uint4*)&hb[8];
            *(uint4*)&Al[ar][ac]     = *(uint4*)&lb[0];
            *(uint4*)&Al[ar][ac + 8] = *(uint4*)&lb[8];
            f = (const float*)rb;
#pragma unroll
            for (int rr = 0; rr < 4; rr++) {
                __nv_bfloat16 h8[8], l8[8];
#pragma unroll
                for (int j = 0; j < 8; j++) split1(f[rr * 8 + j], h8[j], l8[j]);
                *(uint4*)&Bh[rr * 8 + br][bc] = *(uint4*)&h8[0];
                *(uint4*)&Bl[rr * 8 + br][bc] = *(uint4*)&l8[0];
            }
        }
        __syncthreads();

        // prefetch next tile into registers
        if (k0 + 32 < K) {
#pragma unroll
            for (int i = 0; i < 4; i++)
                ra[i] = *(const float4*)(Ag + (k0 + 32) + i * 4);
#pragma unroll
            for (int rr = 0; rr < 4; rr++) {
                rb[rr * 2 + 0] = *(const float4*)(Bg + (size_t)(k0 + 32 + rr * 8) * N);
                rb[rr * 2 + 1] = *(const float4*)(Bg + (size_t)(k0 + 32 + rr * 8) * N + 4);
            }
        }

#pragma unroll
        for (int ks = 0; ks < 2; ks++) {
            const int kk = ks * 16;
            uint32_t a_h[2][4], a_l[2][4];
#pragma unroll
            for (int mf = 0; mf < 2; mf++) {
                const int r = wm + mf * 16 + (lane & 15);
                const int c = kk + (lane >> 4) * 8;
                ldsm_x4(a_h[mf][0], a_h[mf][1], a_h[mf][2], a_h[mf][3], &Ah[r][c]);
                ldsm_x4(a_l[mf][0], a_l[mf][1], a_l[mf][2], a_l[mf][3], &Al[r][c]);
            }
#pragma unroll
            for (int nf = 0; nf < 8; nf++) {
                const int krow = kk + (lane & 15);
                const int nc = wn + nf * 8;
                uint32_t bh0, bh1, bl0, bl1;
                ldsm_x2_trans(bh0, bh1, &Bh[krow][nc]);
                ldsm_x2_trans(bl0, bl1, &Bl[krow][nc]);
#pragma unroll
                for (int mf = 0; mf < 2; mf++) {
                    mma_bf16(acc[mf][nf], a_h[mf], bh0, bh1);
                    mma_bf16(acc[mf][nf], a_h[mf], bl0, bl1);
                    mma_bf16(acc[mf][nf], a_l[mf], bh0, bh1);
                }
            }
        }
        __syncthreads();
    }

    // epilogue: +bias, write fp32
#pragma unroll
    for (int mf = 0; mf < 2; mf++) {
#pragma unroll
        for (int nf = 0; nf < 8; nf++) {
            const int r = row0 + wm + mf * 16 + (lane >> 2);
            const int c = col0 + wn + nf * 8 + (lane & 3) * 2;
            const float bx = bias[c], by = bias[c + 1];
            float2 o0 = make_float2(acc[mf][nf][0] + bx, acc[mf][nf][1] + by);
            float2 o1 = make_float2(acc[mf][nf][2] + bx, acc[mf][nf][3] + by);
            *(float2*)&C[(size_t)r * N + c] = o0;
            *(float2*)&C[(size_t)(r + 8) * N + c] = o1;
        }
    }
}

// ---------------- RoPE + head split + hi/lo presplit -------------------------
__global__ __launch_bounds__(256) void rope_split_kernel() {
    const int i = blockIdx.x * 256 + threadIdx.x;
    const int j = i & 31;
    const int h = (i >> 5) & 15;
    const int s = (i >> 9) & 2047;
    const int b = i >> 20;
    const float* base = g_qkv + ((size_t)(b * SS + s)) * (3 * DD) + h * DH;

    const float ex = (float)(2 * j) / 64.0f;
    const float scale = 1.0f / powf(10000.0f, ex);
    const float ang = (float)s * scale;
    const float c = cosf(ang), sn = sinf(ang);

    const size_t ob = (((size_t)(b * HH + h)) * SS + s) * DH;
    float q1 = base[j], q2 = base[j + 32];
    g_qs[ob + j]      = q1 * c - q2 * sn;
    g_qs[ob + j + 32] = q2 * c + q1 * sn;

    __nv_bfloat16 hh, ll;
    float k1 = base[DD + j], k2 = base[DD + j + 32];
    split1(k1 * c - k2 * sn, hh, ll);
    g_kh[ob + j] = hh;      g_kl[ob + j] = ll;
    split1(k2 * c + k1 * sn, hh, ll);
    g_kh[ob + j + 32] = hh; g_kl[ob + j + 32] = ll;

    split1(base[2 * DD + j], hh, ll);
    g_vh[ob + j] = hh;      g_vl[ob + j] = ll;
    split1(base[2 * DD + j + 32], hh, ll);
    g_vh[ob + j + 32] = hh; g_vl[ob + j + 32] = ll;
}

// ---------------- bias transpose + mask -> bf16 (no smem) --------------------
__global__ __launch_bounds__(256) void biast3_kernel(
    const float* __restrict__ bias, const void* __restrict__ mask)
{
    const int b = blockIdx.z, q = blockIdx.y;
    const int k0 = (blockIdx.x * 256 + threadIdx.x) * 2;
    const float* src = bias + (((size_t)(b * SS + q)) * SS + k0) * HH;
    const int kind = g_mask_kind;
    const bool m0 = mask_at(mask, kind, b * SS + k0);
    const bool m1 = mask_at(mask, kind, b * SS + k0 + 1);

    float f[32];
#pragma unroll
    for (int i = 0; i < 8; i++) *(float4*)&f[i * 4] = ((const float4*)src)[i];

    const __nv_bfloat16 NINF = __float2bfloat16(-INFINITY);
    const size_t outbase = ((size_t)b * HH * SS + q) * SS + k0;
#pragma unroll
    for (int h = 0; h < HH; h++) {
        __nv_bfloat162 pk;
        pk.x = m0 ? __float2bfloat16(f[h]) : NINF;
        pk.y = m1 ? __float2bfloat16(f[16 + h]) : NINF;
        *(__nv_bfloat162*)&g_bt[outbase + (size_t)h * SS * SS] = pk;
    }
}

// ---------------- fused flash attention --------------------------------------
// 128 threads (4 warps), q-tile 64 -> 2 CTAs/SM co-resident.
// k-tiles of 64, cp.async double-buffered.
#define TILE_BUF 9216
#define OFF_KH 0
#define OFF_KL 18432
#define OFF_VH 36864
#define OFF_VL 55296

__global__ __launch_bounds__(128) void flash_kernel() {
    extern __shared__ __align__(16) char sm[];
    const uint32_t smem_base = (uint32_t)__cvta_generic_to_shared(sm);

    const int bh = blockIdx.y;
    const int b = bh >> 4, h = bh & 15;
    const int q0 = blockIdx.x * 64;
    const int t = threadIdx.x;
    const int w = t >> 5, lane = t & 31;
    const int l4 = lane >> 2, lm4 = lane & 3;

    const float* Qg = g_qs + (size_t)bh * SS * DH;
    const __nv_bfloat16* Khg = g_kh + (size_t)bh * SS * DH;
    const __nv_bfloat16* Klg = g_kl + (size_t)bh * SS * DH;
    const __nv_bfloat16* Vhg = g_vh + (size_t)bh * SS * DH;
    const __nv_bfloat16* Vlg = g_vl + (size_t)bh * SS * DH;
    const __nv_bfloat16* Bt = g_bt + (size_t)bh * SS * SS;

    const int qrow = q0 + w * 16 + l4;

    const int cr0 = t >> 3, cc = (t & 7) * 8;

#define COPY_TILE(kt, buf)                                                          \
    {                                                                               \
        const int kb = (kt) * 64;                                                   \
        _Pragma("unroll")                                                           \
        for (int ii = 0; ii < 4; ii++) {                                            \
            const int r = cr0 + ii * 16;                                            \
            const uint32_t d = smem_base + (buf) * TILE_BUF + r * 144 + cc * 2;     \
            CP_ASYNC16(d + OFF_KH, Khg + (size_t)(kb + r) * DH + cc);               \
            CP_ASYNC16(d + OFF_KL, Klg + (size_t)(kb + r) * DH + cc);               \
            CP_ASYNC16(d + OFF_VH, Vhg + (size_t)(kb + r) * DH + cc);               \
            CP_ASYNC16(d + OFF_VL, Vlg + (size_t)(kb + r) * DH + cc);               \
        }                                                                           \
        CP_COMMIT();                                                                \
    }

    uint32_t aQh[4][4], aQl[4][4];
#pragma unroll
    for (int kc = 0; kc < 4; kc++) {
        const int c0 = kc * 16 + 2 * lm4;
        float2 x0 = *(const float2*)&Qg[(size_t)qrow * DH + c0];
        float2 x1 = *(const float2*)&Qg[(size_t)(qrow + 8) * DH + c0];
        float2 x2 = *(const float2*)&Qg[(size_t)qrow * DH + c0 + 8];
        float2 x3 = *(const float2*)&Qg[(size_t)(qrow + 8) * DH + c0 + 8];
        splitpack(x0.x * 0.125f, x0.y * 0.125f, aQh[kc][0], aQl[kc][0]);
        splitpack(x1.x * 0.125f, x1.y * 0.125f, aQh[kc][1], aQl[kc][1]);
        splitpack(x2.x * 0.125f, x2.y * 0.125f, aQh[kc][2], aQl[kc][2]);
        splitpack(x3.x * 0.125f, x3.y * 0.125f, aQh[kc][3], aQl[kc][3]);
    }

    COPY_TILE(0, 0);

    float m0 = -INFINITY, m1 = -INFINITY;
    float l0 = 0.f, l1 = 0.f;
    float O[8][4];
#pragma unroll
    for (int nt = 0; nt < 8; nt++)
#pragma unroll
        for (int j = 0; j < 4; j++) O[nt][j] = 0.f;

    for (int kt = 0; kt < SS / 64; kt++) {
        const int buf = kt & 1;
        const int k0 = kt * 64;
        if (kt + 1 < SS / 64) {
            COPY_TILE(kt + 1, buf ^ 1);
            CP_WAIT(1);
        } else {
            CP_WAIT(0);
        }
        __syncthreads();

        const __nv_bfloat16* sKh = (const __nv_bfloat16*)(sm + OFF_KH) + buf * 4608;
        const __nv_bfloat16* sKl = (const __nv_bfloat16*)(sm + OFF_KL) + buf * 4608;
        const __nv_bfloat16* sVh = (const __nv_bfloat16*)(sm + OFF_VH) + buf * 4608;
        const __nv_bfloat16* sVl = (const __nv_bfloat16*)(sm + OFF_VL) + buf * 4608;

        float c_[8][4];
#pragma unroll
        for (int nt = 0; nt < 8; nt++) {
            const int kc0 = k0 + nt * 8 + 2 * lm4;
            __nv_bfloat162 b01 = *(const __nv_bfloat162*)&Bt[(size_t)qrow * SS + kc0];
            __nv_bfloat162 b23 = *(const __nv_bfloat162*)&Bt[(size_t)(qrow + 8) * SS + kc0];
            c_[nt][0] = __bfloat162float(b01.x); c_[nt][1] = __bfloat162float(b01.y);
            c_[nt][2] = __bfloat162float(b23.x); c_[nt][3] = __bfloat162float(b23.y);
        }
#pragma unroll
        for (int nt = 0; nt < 8; nt++) {
#pragma unroll
            for (int kc = 0; kc < 4; kc++) {
                const int kr = nt * 8 + l4;
                const int dc = kc * 16 + 2 * lm4;
                uint32_t bh0 = *(const uint32_t*)&sKh[kr * 72 + dc];
                uint32_t bh1 = *(const uint32_t*)&sKh[kr * 72 + dc + 8];
                uint32_t bl0 = *(const uint32_t*)&sKl[kr * 72 + dc];
                uint32_t bl1 = *(const uint32_t*)&sKl[kr * 72 + dc + 8];
                mma_bf16(c_[nt], aQh[kc], bh0, bh1);
                mma_bf16(c_[nt], aQh[kc], bl0, bl1);
                mma_bf16(c_[nt], aQl[kc], bh0, bh1);
            }
        }

        float tm0 = -INFINITY, tm1 = -INFINITY;
#pragma unroll
        for (int nt = 0; nt < 8; nt++) {
            tm0 = fmaxf(tm0, fmaxf(c_[nt][0], c_[nt][1]));
            tm1 = fmaxf(tm1, fmaxf(c_[nt][2], c_[nt][3]));
        }
        tm0 = fmaxf(tm0, __shfl_xor_sync(0xFFFFFFFFu, tm0, 1));
        tm0 = fmaxf(tm0, __shfl_xor_sync(0xFFFFFFFFu, tm0, 2));
        tm1 = fmaxf(tm1, __shfl_xor_sync(0xFFFFFFFFu, tm1, 1));
        tm1 = fmaxf(tm1, __shfl_xor_sync(0xFFFFFFFFu, tm1, 2));

        const float nm0 = fmaxf(m0, tm0), nm1 = fmaxf(m1, tm1);
        const float sc0 = exp2f((m0 - nm0) * LOG2E);
        const float sc1 = exp2f((m1 - nm1) * LOG2E);
        m0 = nm0; m1 = nm1;

        float rs0 = 0.f, rs1 = 0.f;
#pragma unroll
        for (int nt = 0; nt < 8; nt++) {
            float p0 = exp2f((c_[nt][0] - m0) * LOG2E);
            float p1 = exp2f((c_[nt][1] - m0) * LOG2E);
            float p2 = exp2f((c_[nt][2] - m1) * LOG2E);
            float p3 = exp2f((c_[nt][3] - m1) * LOG2E);
            c_[nt][0] = p0; c_[nt][1] = p1; c_[nt][2] = p2; c_[nt][3] = p3;
            rs0 += p0 + p1; rs1 += p2 + p3;
        }
        rs0 += __shfl_xor_sync(0xFFFFFFFFu, rs0, 1);
        rs0 += __shfl_xor_sync(0xFFFFFFFFu, rs0, 2);
        rs1 += __shfl_xor_sync(0xFFFFFFFFu, rs1, 1);
        rs1 += __shfl_xor_sync(0xFFFFFFFFu, rs1, 2);
        l0 = l0 * sc0 + rs0;
        l1 = l1 * sc1 + rs1;

#pragma unroll
        for (int nt = 0; nt < 8; nt++) {
            O[nt][0] *= sc0; O[nt][1] *= sc0;
            O[nt][2] *= sc1; O[nt][3] *= sc1;
        }

        uint32_t aPh[4][4], aPl[4][4];
#pragma unroll
        for (int kc = 0; kc < 4; kc++) {
            splitpack(c_[2 * kc][0],     c_[2 * kc][1],     aPh[kc][0], aPl[kc][0]);
            splitpack(c_[2 * kc][2],     c_[2 * kc][3],     aPh[kc][1], aPl[kc][1]);
            splitpack(c_[2 * kc + 1][0], c_[2 * kc + 1][1], aPh[kc][2], aPl[kc][2]);
            splitpack(c_[2 * kc + 1][2], c_[2 * kc + 1][3], aPh[kc][3], aPl[kc][3]);
        }

#pragma unroll
        for (int nt = 0; nt < 8; nt++) {
#pragma unroll
            for (int kc = 0; kc < 4; kc++) {
                const int vr = kc * 16 + (lane & 15);
                uint32_t bh0, bh1, bl0, bl1;
                ldsm_x2_trans(bh0, bh1, &sVh[vr * 72 + nt * 8]);
                ldsm_x2_trans(bl0, bl1, &sVl[vr * 72 + nt * 8]);
                mma_bf16(O[nt], aPh[kc], bh0, bh1);
                mma_bf16(O[nt], aPh[kc], bl0, bl1);
                mma_bf16(O[nt], aPl[kc], bh0, bh1);
            }
        }
        __syncthreads();
    }

    const float inv0 = 1.0f / l0, inv1 = 1.0f / l1;
#pragma unroll
    for (int nt = 0; nt < 8; nt++) {
        const int col = h * DH + nt * 8 + 2 * lm4;
        float2 o0 = make_float2(O[nt][0] * inv0, O[nt][1] * inv0);
        float2 o1 = make_float2(O[nt][2] * inv1, O[nt][3] * inv1);
        *(float2*)&g_ao[((size_t)(b * SS + qrow)) * DD + col] = o0;
        *(float2*)&g_ao[((size_t)(b * SS + qrow + 8)) * DD + col] = o1;
    }
}

// ---------------- launch ------------------------------------------------------
extern "C" void kernel_launch(void* const* d_in, const int* in_sizes, int n_in,
                              void* d_out, int out_size) {
    const float* x    = (const float*)d_in[0];
    const void*  mask = d_in[1];
    const float* bias = (const float*)d_in[2];
    const float* Wqkv = (const float*)d_in[3];
    const float* bqkv = (const float*)d_in[4];
    const float* Wout = (const float*)d_in[5];
    const float* bout = (const float*)d_in[6];
    float* out = (float*)d_out;

    float *qkv = nullptr, *ao = nullptr;
    cudaGetSymbolAddress((void**)&qkv, g_qkv);
    cudaGetSymbolAddress((void**)&ao, g_ao);

    cudaFuncSetAttribute(flash_kernel,
                         cudaFuncAttributeMaxDynamicSharedMemorySize, 73728);

    detect_mask_kind_kernel<<<1, 256>>>((const unsigned int*)mask);

    // qkv = x @ W_qkv + b_qkv   (64x128 tiles, 3 CTAs/SM)
    mma_gemm_bias_kernel<<<dim3(24, 64), 128>>>(x, Wqkv, bqkv, qkv, BB * SS, 3 * DD, DD);

    // head split + RoPE + hi/lo presplit of K,V
    rope_split_kernel<<<(BB * SS * HH * 32) / 256, 256>>>();

    // biasT + mask -> bf16 (register transpose, no smem)
    biast3_kernel<<<dim3(SS / 512, SS, BB), 256>>>(bias, mask);

    // fused attention (128-thread CTAs, q-tile 64 -> 2 CTAs/SM)
    flash_kernel<<<dim3(SS / 64, BB * HH), 128, 73728>>>();

    // out = a_out @ W_out + b_out
    mma_gemm_bias_kernel<<<dim3(8, 64), 128>>>(ao, Wout, bout, out, BB * SS, DD, DD);
}